// round 7
// baseline (speedup 1.0000x reference)
#include <cuda_runtime.h>
#include <cuda_bf16.h>
#include <math.h>
#include <stdint.h>

#define EMBED 512
#define HEADS 8
#define HDIM 64
#define SEQL 65
#define NPATCH 64
#define PFEAT 48
#define HID 1024
#define NCLS 10
#define BATCH 2048
#define MTOT (BATCH * SEQL)   // 133120

// global scratch (no allocations allowed)
__device__ __align__(16) __nv_bfloat16 g_shi[(size_t)MTOT * EMBED];
__device__ __align__(16) __nv_bfloat16 g_slo[(size_t)MTOT * EMBED];
__device__ __align__(16) __nv_bfloat16 g_whi[EMBED * EMBED];
__device__ __align__(16) __nv_bfloat16 g_wlo[EMBED * EMBED];
__device__ __align__(16) __nv_bfloat16 g_qhi[(size_t)MTOT * EMBED];
__device__ __align__(16) __nv_bfloat16 g_qlo[(size_t)MTOT * EMBED];
__device__ __align__(16) float g_ctpre[BATCH * EMBED];
__device__ __align__(16) float g_ct[BATCH * EMBED];
__device__ __align__(16) float g_h[BATCH * HID];

// ---------------- helpers ----------------
__device__ __forceinline__ void ffma2(unsigned long long& d,
                                      unsigned long long a,
                                      unsigned long long b) {
    asm("fma.rn.f32x2 %0, %1, %2, %0;" : "+l"(d) : "l"(a), "l"(b));
}
__device__ __forceinline__ unsigned long long packdup(float x) {
    unsigned long long r;
    asm("mov.b64 %0, {%1, %2};" : "=l"(r) : "f"(x), "f"(x));
    return r;
}
__device__ __forceinline__ unsigned long long pack2f(float a, float b) {
    unsigned long long r;
    asm("mov.b64 %0, {%1, %2};" : "=l"(r) : "f"(a), "f"(b));
    return r;
}
__device__ __forceinline__ float2 unpack2(unsigned long long v) {
    float2 r;
    asm("mov.b64 {%0, %1}, %2;" : "=f"(r.x), "=f"(r.y) : "l"(v));
    return r;
}
// fast exp: degree-5 Taylor of 2^f, rel err ~2.4e-6
__device__ __forceinline__ float fexp(float x) {
    x = fmaxf(x, -87.0f);
    float y = x * 1.4426950408889634f;
    int ir = __float2int_rn(y);
    float f = y - (float)ir;
    float p = 1.3333558146428443e-3f;
    p = fmaf(p, f, 9.618129107628477e-3f);
    p = fmaf(p, f, 5.55041086648216e-2f);
    p = fmaf(p, f, 2.402265069591007e-1f);
    p = fmaf(p, f, 6.931471805599453e-1f);
    p = fmaf(p, f, 1.0f);
    return p * __int_as_float((ir + 127) << 23);
}
__device__ __forceinline__ void mma16816(float* c, const uint32_t* a,
                                         const uint32_t* b) {
    asm volatile(
        "mma.sync.aligned.m16n8k16.row.col.f32.bf16.bf16.f32 "
        "{%0,%1,%2,%3}, {%4,%5,%6,%7}, {%8,%9}, {%0,%1,%2,%3};"
        : "+f"(c[0]), "+f"(c[1]), "+f"(c[2]), "+f"(c[3])
        : "r"(a[0]), "r"(a[1]), "r"(a[2]), "r"(a[3]), "r"(b[0]), "r"(b[1]));
}
__device__ __forceinline__ void ldsm4(uint32_t* r, uint32_t addr) {
    asm volatile("ldmatrix.sync.aligned.m8n8.x4.shared.b16 {%0,%1,%2,%3}, [%4];"
                 : "=r"(r[0]), "=r"(r[1]), "=r"(r[2]), "=r"(r[3]) : "r"(addr));
}
__device__ __forceinline__ void cp16(uint32_t dst_smem, const void* src) {
    asm volatile("cp.async.ca.shared.global [%0], [%1], 16;"
                 :: "r"(dst_smem), "l"(src));
}
__device__ __forceinline__ void cpcommit() { asm volatile("cp.async.commit_group;"); }
__device__ __forceinline__ void cpwait1()  { asm volatile("cp.async.wait_group 1;"); }
__device__ __forceinline__ void cpwait0()  { asm volatile("cp.async.wait_group 0;"); }

__device__ __forceinline__ void split_store2(__nv_bfloat16* Chi, __nv_bfloat16* Clo,
                                             size_t off, float v0, float v1) {
    __nv_bfloat16 h0 = __float2bfloat16(v0), h1 = __float2bfloat16(v1);
    __nv_bfloat16 l0 = __float2bfloat16(v0 - __bfloat162float(h0));
    __nv_bfloat16 l1 = __float2bfloat16(v1 - __bfloat162float(h1));
    __nv_bfloat162 H; H.x = h0; H.y = h1;
    __nv_bfloat162 L; L.x = l0; L.y = l1;
    *(__nv_bfloat162*)(Chi + off) = H;
    *(__nv_bfloat162*)(Clo + off) = L;
}

// ---------------------------------------------------------------------------
// K0: split wq into hi/lo bf16
// ---------------------------------------------------------------------------
__global__ __launch_bounds__(256) void wprep_kernel(
    const float* __restrict__ wq, __nv_bfloat16* __restrict__ whi,
    __nv_bfloat16* __restrict__ wlo)
{
    int i = blockIdx.x * 256 + threadIdx.x;
    float v = wq[i];
    __nv_bfloat16 h = __float2bfloat16(v);
    whi[i] = h;
    wlo[i] = __float2bfloat16(v - __bfloat162float(h));
}

// ---------------------------------------------------------------------------
// K1: one CTA per batch element: patchify -> emb GEMM (FFMA2) -> +pos -> hi/lo
// ---------------------------------------------------------------------------
__global__ __launch_bounds__(256) void seq_kernel(
    const float* __restrict__ x, const float* __restrict__ proj_w,
    const float* __restrict__ proj_b, const float* __restrict__ cls,
    const float* __restrict__ pos, __nv_bfloat16* __restrict__ shi_,
    __nv_bfloat16* __restrict__ slo_)
{
    __shared__ float ps[NPATCH * 49];
    __shared__ __align__(8) float wt[PFEAT * 66];

    const int b = blockIdx.x;
    const int t = threadIdx.x;
    const int tx = t & 31, ty = t >> 5;
    __nv_bfloat16* shi = shi_ + (size_t)b * SEQL * EMBED;
    __nv_bfloat16* slo = slo_ + (size_t)b * SEQL * EMBED;

    const float* xb = x + (size_t)b * 3 * 32 * 32;
    for (int idx = t; idx < NPATCH * PFEAT; idx += 256) {
        int n = idx / PFEAT, f = idx % PFEAT;
        int c = f >> 4, r4 = (f >> 2) & 3, c4 = f & 3;
        int py = n >> 3, px = n & 7;
        ps[n * 49 + f] = xb[c * 1024 + (py * 4 + r4) * 32 + (px * 4 + c4)];
    }
    for (int e = t; e < EMBED; e += 256) {
        float v = cls[e] + pos[e];
        __nv_bfloat16 h = __float2bfloat16(v);
        shi[e] = h; slo[e] = __float2bfloat16(v - __bfloat162float(h));
    }
    __syncthreads();

    for (int e0 = 0; e0 < EMBED; e0 += 64) {
        {
            int e = t >> 2, fc = (t & 3) * 12;
            const float4* src = (const float4*)(proj_w + (size_t)(e0 + e) * PFEAT + fc);
            #pragma unroll
            for (int j = 0; j < 3; j++) {
                float4 v = src[j];
                wt[(fc + j * 4 + 0) * 66 + e] = v.x;
                wt[(fc + j * 4 + 1) * 66 + e] = v.y;
                wt[(fc + j * 4 + 2) * 66 + e] = v.z;
                wt[(fc + j * 4 + 3) * 66 + e] = v.w;
            }
        }
        __syncthreads();
        int e1 = e0 + 2 * tx;
        unsigned long long acc2[8];
        {
            unsigned long long pb = pack2f(proj_b[e1], proj_b[e1 + 1]);
            #pragma unroll
            for (int i = 0; i < 8; i++) acc2[i] = pb;
        }
        #pragma unroll 4
        for (int f = 0; f < PFEAT; f++) {
            unsigned long long wv = *(const unsigned long long*)&wt[f * 66 + 2 * tx];
            #pragma unroll
            for (int i = 0; i < 8; i++)
                ffma2(acc2[i], packdup(ps[(ty + 8 * i) * 49 + f]), wv);
        }
        #pragma unroll
        for (int i = 0; i < 8; i++) {
            int n = ty + 8 * i;
            float2 av = unpack2(acc2[i]);
            float v0 = av.x + pos[(1 + n) * EMBED + e1];
            float v1 = av.y + pos[(1 + n) * EMBED + e1 + 1];
            __nv_bfloat16 h0 = __float2bfloat16(v0);
            __nv_bfloat16 h1 = __float2bfloat16(v1);
            shi[(1 + n) * EMBED + e1]     = h0;
            shi[(1 + n) * EMBED + e1 + 1] = h1;
            slo[(1 + n) * EMBED + e1]     = __float2bfloat16(v0 - __bfloat162float(h0));
            slo[(1 + n) * EMBED + e1 + 1] = __float2bfloat16(v1 - __bfloat162float(h1));
        }
        __syncthreads();
    }
}

// ---------------------------------------------------------------------------
// K2: q GEMM via mma.sync + ldmatrix, cp.async double-buffered.
// CTA 128x128, K chunk 32, 8 warps (4m x 2n), warp tile 32x64.
// ---------------------------------------------------------------------------
#define QSTR 40
#define NCH 16

__global__ __launch_bounds__(256, 2) void qgemm_mma_kernel(
    const __nv_bfloat16* __restrict__ Ahi, const __nv_bfloat16* __restrict__ Alo,
    const __nv_bfloat16* __restrict__ Whi, const __nv_bfloat16* __restrict__ Wlo,
    const float* __restrict__ bias,
    __nv_bfloat16* __restrict__ Chi, __nv_bfloat16* __restrict__ Clo)
{
    __shared__ __align__(16) __nv_bfloat16 sAh[2][128 * QSTR];
    __shared__ __align__(16) __nv_bfloat16 sAl[2][128 * QSTR];
    __shared__ __align__(16) __nv_bfloat16 sWh[2][128 * QSTR];
    __shared__ __align__(16) __nv_bfloat16 sWl[2][128 * QSTR];

    const int t = threadIdx.x;
    const int wid = t >> 5, lane = t & 31;
    const int gid = lane >> 2, tig = lane & 3;
    const int wm = wid & 3, wn = wid >> 2;
    const int m0 = blockIdx.y * 128, n0 = blockIdx.x * 128;

    float acc[2][8][4];
    #pragma unroll
    for (int i = 0; i < 2; i++)
        #pragma unroll
        for (int j = 0; j < 8; j++)
            #pragma unroll
            for (int k = 0; k < 4; k++) acc[i][j][k] = 0.f;

    const int r0 = t >> 2, kq = (t & 3) * 8;
    const uint32_t stg = 128 * QSTR * 2;
    const uint32_t rowB = 64 * QSTR * 2;
    const uint32_t bAh = (uint32_t)__cvta_generic_to_shared(&sAh[0][r0 * QSTR + kq]);
    const uint32_t bAl = (uint32_t)__cvta_generic_to_shared(&sAl[0][r0 * QSTR + kq]);
    const uint32_t bWh = (uint32_t)__cvta_generic_to_shared(&sWh[0][r0 * QSTR + kq]);
    const uint32_t bWl = (uint32_t)__cvta_generic_to_shared(&sWl[0][r0 * QSTR + kq]);

    auto issue = [&](int c, int s) {
        size_t ko = (size_t)c * 32 + kq;
        const uint32_t so = s * stg;
        cp16(bAh + so,        Ahi + (size_t)(m0 + r0) * EMBED + ko);
        cp16(bAh + so + rowB, Ahi + (size_t)(m0 + r0 + 64) * EMBED + ko);
        cp16(bAl + so,        Alo + (size_t)(m0 + r0) * EMBED + ko);
        cp16(bAl + so + rowB, Alo + (size_t)(m0 + r0 + 64) * EMBED + ko);
        cp16(bWh + so,        Whi + (size_t)(n0 + r0) * EMBED + ko);
        cp16(bWh + so + rowB, Whi + (size_t)(n0 + r0 + 64) * EMBED + ko);
        cp16(bWl + so,        Wlo + (size_t)(n0 + r0) * EMBED + ko);
        cp16(bWl + so + rowB, Wlo + (size_t)(n0 + r0 + 64) * EMBED + ko);
        cpcommit();
    };

    const int aoff = (wm * 32 + (lane & 15)) * QSTR + (lane >> 4) * 8;
    const int boffn = wn * 64 + ((lane >> 4) << 3) + (lane & 7);
    const int boffk = ((lane >> 3) & 1) * 8;

    const uint32_t baseAh = (uint32_t)__cvta_generic_to_shared(&sAh[0][0]);
    const uint32_t baseAl = (uint32_t)__cvta_generic_to_shared(&sAl[0][0]);
    const uint32_t baseWh = (uint32_t)__cvta_generic_to_shared(&sWh[0][0]);
    const uint32_t baseWl = (uint32_t)__cvta_generic_to_shared(&sWl[0][0]);

    issue(0, 0);
    for (int c = 0; c < NCH; c++) {
        const int s = c & 1;
        if (c + 1 < NCH) { issue(c + 1, (c + 1) & 1); cpwait1(); }
        else             { cpwait0(); }
        __syncthreads();
        const uint32_t so = s * stg;
        #pragma unroll
        for (int ks = 0; ks < 2; ks++) {
            const int k0 = ks * 16;
            uint32_t ah[2][4], al[2][4];
            #pragma unroll
            for (int mt = 0; mt < 2; mt++) {
                uint32_t ad = (uint32_t)((aoff + mt * 16 * QSTR + k0) * 2);
                ldsm4(ah[mt], baseAh + so + ad);
                ldsm4(al[mt], baseAl + so + ad);
            }
            #pragma unroll
            for (int p = 0; p < 4; p++) {
                uint32_t bh[4], bl[4];
                uint32_t bd = (uint32_t)(((boffn + p * 16) * QSTR + k0 + boffk) * 2);
                ldsm4(bh, baseWh + so + bd);
                ldsm4(bl, baseWl + so + bd);
                #pragma unroll
                for (int mt = 0; mt < 2; mt++) {
                    mma16816(acc[mt][2 * p],     ah[mt], bh);
                    mma16816(acc[mt][2 * p],     ah[mt], bl);
                    mma16816(acc[mt][2 * p],     al[mt], bh);
                    mma16816(acc[mt][2 * p + 1], ah[mt], bh + 2);
                    mma16816(acc[mt][2 * p + 1], ah[mt], bl + 2);
                    mma16816(acc[mt][2 * p + 1], al[mt], bh + 2);
                }
            }
        }
        __syncthreads();
    }

    #pragma unroll
    for (int mt = 0; mt < 2; mt++) {
        int r = m0 + wm * 32 + mt * 16 + gid;
        #pragma unroll
        for (int nt = 0; nt < 8; nt++) {
            int n = n0 + wn * 64 + nt * 8 + tig * 2;
            float b0 = bias[n], b1 = bias[n + 1];
            split_store2(Chi, Clo, (size_t)r * EMBED + n,
                         acc[mt][nt][0] + b0, acc[mt][nt][1] + b1);
            split_store2(Chi, Clo, (size_t)(r + 8) * EMBED + n,
                         acc[mt][nt][2] + b0, acc[mt][nt][3] + b1);
        }
    }
}

// ---------------------------------------------------------------------------
// K3: per (b,h): scores via bf16 mma + fp32 qf for borders/softmax/att0
// ---------------------------------------------------------------------------
#define ASTR 72

__global__ __launch_bounds__(128) void attn_kernel(
    const __nv_bfloat16* __restrict__ qhi, const __nv_bfloat16* __restrict__ qlo,
    float* __restrict__ ctpre)
{
    __shared__ __align__(16) __nv_bfloat16 sQh[SEQL * ASTR];
    __shared__ __align__(16) __nv_bfloat16 sQl[SEQL * ASTR];
    __shared__ __align__(16) float qf[SEQL][68];
    __shared__ float sc[SEQL][68];
    __shared__ float w0s[68];

    const int b = blockIdx.y, h = blockIdx.x;
    const int t = threadIdx.x, lane = t & 31, wid = t >> 5;
    const int gid = lane >> 2, tig = lane & 3;
    const __nv_bfloat16* ph = qhi + (size_t)b * SEQL * EMBED + h * HDIM;
    const __nv_bfloat16* pl = qlo + (size_t)b * SEQL * EMBED + h * HDIM;

    // load + fp32 reconstruct (one-time cvts)
    for (int idx = t; idx < SEQL * 8; idx += 128) {
        int row = idx >> 3, c8 = (idx & 7) * 8;
        uint4 vh = *(const uint4*)(ph + (size_t)row * EMBED + c8);
        uint4 vl = *(const uint4*)(pl + (size_t)row * EMBED + c8);
        *(uint4*)(sQh + row * ASTR + c8) = vh;
        *(uint4*)(sQl + row * ASTR + c8) = vl;
        const __nv_bfloat162* hp = (const __nv_bfloat162*)&vh;
        const __nv_bfloat162* lp = (const __nv_bfloat162*)&vl;
        float4 f0, f1;
        f0.x = __bfloat162float(hp[0].x) + __bfloat162float(lp[0].x);
        f0.y = __bfloat162float(hp[0].y) + __bfloat162float(lp[0].y);
        f0.z = __bfloat162float(hp[1].x) + __bfloat162float(lp[1].x);
        f0.w = __bfloat162float(hp[1].y) + __bfloat162float(lp[1].y);
        f1.x = __bfloat162float(hp[2].x) + __bfloat162float(lp[2].x);
        f1.y = __bfloat162float(hp[2].y) + __bfloat162float(lp[2].y);
        f1.z = __bfloat162float(hp[3].x) + __bfloat162float(lp[3].x);
        f1.w = __bfloat162float(hp[3].y) + __bfloat162float(lp[3].y);
        *(float4*)&qf[row][c8]     = f0;
        *(float4*)&qf[row][c8 + 4] = f1;
    }
    __syncthreads();

    // 64x64 score block via mma: warp w -> rows w*16..+15
    const uint32_t baseQh = (uint32_t)__cvta_generic_to_shared(&sQh[0]);
    const uint32_t baseQl = (uint32_t)__cvta_generic_to_shared(&sQl[0]);
    const int m0 = wid * 16;
    const int aoff = (m0 + (lane & 15)) * ASTR + (lane >> 4) * 8;
    const int boffn = ((lane >> 4) << 3) + (lane & 7);
    const int boffk = ((lane >> 3) & 1) * 8;

    float acc[8][4];
    #pragma unroll
    for (int j = 0; j < 8; j++)
        #pragma unroll
        for (int k = 0; k < 4; k++) acc[j][k] = 0.f;

    #pragma unroll
    for (int kc = 0; kc < 4; kc++) {
        const int k0 = kc * 16;
        uint32_t ah[4], al[4];
        ldsm4(ah, baseQh + (uint32_t)((aoff + k0) * 2));
        ldsm4(al, baseQl + (uint32_t)((aoff + k0) * 2));
        #pragma unroll
        for (int p = 0; p < 4; p++) {
            uint32_t bh[4], bl[4];
            uint32_t bd = (uint32_t)(((boffn + p * 16) * ASTR + k0 + boffk) * 2);
            ldsm4(bh, baseQh + bd);
            ldsm4(bl, baseQl + bd);
            mma16816(acc[2 * p],     ah, bh);
            mma16816(acc[2 * p],     ah, bl);
            mma16816(acc[2 * p],     al, bh);
            mma16816(acc[2 * p + 1], ah, bh + 2);
            mma16816(acc[2 * p + 1], ah, bl + 2);
            mma16816(acc[2 * p + 1], al, bh + 2);
        }
    }
    #pragma unroll
    for (int nt = 0; nt < 8; nt++) {
        int rr = m0 + gid, cc = nt * 8 + tig * 2;
        sc[rr][cc]         = acc[nt][0] * 0.125f;
        sc[rr][cc + 1]     = acc[nt][1] * 0.125f;
        sc[rr + 8][cc]     = acc[nt][2] * 0.125f;
        sc[rr + 8][cc + 1] = acc[nt][3] * 0.125f;
    }
    // row 64 via fp32 qf (t = column 0..64)
    if (t < SEQL) {
        float a = 0.f;
        #pragma unroll 8
        for (int k = 0; k < HDIM; k++) a += qf[64][k] * qf[t][k];
        sc[64][t] = a * 0.125f;
    }
    __syncthreads();
    if (t < 64) sc[t][64] = sc[64][t];   // symmetry
    __syncthreads();

    if (t < SEQL) {
        float m = -1e30f;
        for (int s = 0; s < SEQL; s++) m = fmaxf(m, sc[s][t]);
        float Z = 0.f;
        for (int s = 0; s < SEQL; s++) Z += fexp(sc[s][t] - m);
        w0s[t] = fexp(sc[0][t] - m) / Z;
    }
    __syncthreads();

    if (t < HDIM) {
        float a = 0.f;
        #pragma unroll 8
        for (int s = 0; s < SEQL; s++) a += w0s[s] * qf[s][t];
        ctpre[(size_t)b * EMBED + h * HDIM + t] = a;
    }
}

// ---------------------------------------------------------------------------
// tail GEMM: C = A @ W^T + bias (FFMA2 inner), optional exact GELU
// ---------------------------------------------------------------------------
__global__ __launch_bounds__(256, 2) void gemm_bias_kernel(
    const float* __restrict__ A, const float* __restrict__ W,
    const float* __restrict__ bias, float* __restrict__ C,
    int M, int N, int K, int act)
{
    __shared__ __align__(16) float As[32][68];
    __shared__ __align__(16) float Ws[32][68];
    const int m0 = blockIdx.y * 64, n0 = blockIdx.x * 64;
    const int t = threadIdx.x;
    const int tn = t & 15, tm = t >> 4;
    unsigned long long acc2[4][2];
    #pragma unroll
    for (int i = 0; i < 4; i++) { acc2[i][0] = 0ULL; acc2[i][1] = 0ULL; }

    for (int k0 = 0; k0 < K; k0 += 32) {
        #pragma unroll
        for (int l = 0; l < 2; l++) {
            int i = t + l * 256;
            int row = i >> 3;
            int kk = (i & 7) * 4;
            float4 v = *(const float4*)(A + (size_t)(m0 + row) * K + k0 + kk);
            As[kk + 0][row] = v.x; As[kk + 1][row] = v.y;
            As[kk + 2][row] = v.z; As[kk + 3][row] = v.w;
            float4 u = *(const float4*)(W + (size_t)(n0 + row) * K + k0 + kk);
            Ws[kk + 0][row] = u.x; Ws[kk + 1][row] = u.y;
            Ws[kk + 2][row] = u.z; Ws[kk + 3][row] = u.w;
        }
        __syncthreads();
        #pragma unroll
        for (int k = 0; k < 32; k++) {
            float4 av = *(const float4*)&As[k][tm * 4];
            unsigned long long w0 = *(const unsigned long long*)&Ws[k][tn * 4];
            unsigned long long w1 = *(const unsigned long long*)&Ws[k][tn * 4 + 2];
            ffma2(acc2[0][0], packdup(av.x), w0); ffma2(acc2[0][1], packdup(av.x), w1);
            ffma2(acc2[1][0], packdup(av.y), w0); ffma2(acc2[1][1], packdup(av.y), w1);
            ffma2(acc2[2][0], packdup(av.z), w0); ffma2(acc2[2][1], packdup(av.z), w1);
            ffma2(acc2[3][0], packdup(av.w), w0); ffma2(acc2[3][1], packdup(av.w), w1);
        }
        __syncthreads();
    }
    #pragma unroll
    for (int i = 0; i < 4; i++) {
        int m = m0 + tm * 4 + i;
        #pragma unroll
        for (int jh = 0; jh < 2; jh++) {
            float2 v2 = unpack2(acc2[i][jh]);
            #pragma unroll
            for (int u = 0; u < 2; u++) {
                int n = n0 + tn * 4 + jh * 2 + u;
                float v = (u == 0 ? v2.x : v2.y) + bias[n];
                if (act) v = 0.5f * v * (1.f + erff(v * 0.70710678118654752f));
                C[(size_t)m * N + n] = v;
            }
        }
    }
}

// logits: one CTA per batch row, one warp per class
__global__ __launch_bounds__(320) void logits_kernel(
    const float* __restrict__ h, const float* __restrict__ w2,
    const float* __restrict__ b2, float* __restrict__ out)
{
    int b = blockIdx.x;
    int lane = threadIdx.x & 31, w = threadIdx.x >> 5;
    const float* hb = h + (size_t)b * HID;
    float a = 0.f;
    for (int k = lane; k < HID; k += 32) a += hb[k] * w2[(size_t)w * HID + k];
    #pragma unroll
    for (int o = 16; o > 0; o >>= 1) a += __shfl_xor_sync(0xffffffffu, a, o);
    if (lane == 0) out[(size_t)b * NCLS + w] = a + b2[w];
}

extern "C" void kernel_launch(void* const* d_in, const int* in_sizes, int n_in,
                              void* d_out, int out_size)
{
    const float* x      = (const float*)d_in[0];
    const float* proj_w = (const float*)d_in[1];
    const float* proj_b = (const float*)d_in[2];
    const float* cls    = (const float*)d_in[3];
    const float* pos    = (const float*)d_in[4];
    const float* wq     = (const float*)d_in[5];
    const float* bq     = (const float*)d_in[6];
    const float* wo     = (const float*)d_in[7];
    const float* bo     = (const float*)d_in[8];
    const float* w1     = (const float*)d_in[9];
    const float* b1     = (const float*)d_in[10];
    const float* w2     = (const float*)d_in[11];
    const float* b2     = (const float*)d_in[12];
    float* out = (float*)d_out;

    __nv_bfloat16 *p_shi, *p_slo, *p_whi, *p_wlo, *p_qhi, *p_qlo;
    float *p_ctpre, *p_ct, *p_h;
    cudaGetSymbolAddress((void**)&p_shi, g_shi);
    cudaGetSymbolAddress((void**)&p_slo, g_slo);
    cudaGetSymbolAddress((void**)&p_whi, g_whi);
    cudaGetSymbolAddress((void**)&p_wlo, g_wlo);
    cudaGetSymbolAddress((void**)&p_qhi, g_qhi);
    cudaGetSymbolAddress((void**)&p_qlo, g_qlo);
    cudaGetSymbolAddress((void**)&p_ctpre, g_ctpre);
    cudaGetSymbolAddress((void**)&p_ct, g_ct);
    cudaGetSymbolAddress((void**)&p_h, g_h);

    wprep_kernel<<<EMBED * EMBED / 256, 256>>>(wq, p_whi, p_wlo);
    seq_kernel<<<BATCH, 256>>>(x, proj_w, proj_b, cls, pos, p_shi, p_slo);
    qgemm_mma_kernel<<<dim3(EMBED / 128, MTOT / 128), 256>>>(
        p_shi, p_slo, p_whi, p_wlo, bq, p_qhi, p_qlo);
    attn_kernel<<<dim3(HEADS, BATCH), 128>>>(p_qhi, p_qlo, p_ctpre);
    gemm_bias_kernel<<<dim3(EMBED / 64, BATCH / 64), 256>>>(
        p_ctpre, wo, bo, p_ct, BATCH, EMBED, EMBED, 0);
    gemm_bias_kernel<<<dim3(HID / 64, BATCH / 64), 256>>>(
        p_ct, w1, b1, p_h, BATCH, HID, EMBED, 1);
    logits_kernel<<<BATCH, 320>>>(p_h, w2, b2, out);
}

// round 8
// speedup vs baseline: 1.0861x; 1.0861x over previous
#include <cuda_runtime.h>
#include <cuda_bf16.h>
#include <math.h>
#include <stdint.h>

#define EMBED 512
#define HEADS 8
#define HDIM 64
#define SEQL 65
#define NPATCH 64
#define PFEAT 48
#define HID 1024
#define NCLS 10
#define BATCH 2048
#define MTOT (BATCH * SEQL)   // 133120

// global scratch (no allocations allowed)
__device__ __align__(16) __nv_bfloat16 g_shi[(size_t)MTOT * EMBED];
__device__ __align__(16) __nv_bfloat16 g_slo[(size_t)MTOT * EMBED];
__device__ __align__(16) __nv_bfloat16 g_whi[EMBED * EMBED];
__device__ __align__(16) __nv_bfloat16 g_wlo[EMBED * EMBED];
__device__ __align__(16) __nv_bfloat16 g_wohi[EMBED * EMBED];
__device__ __align__(16) __nv_bfloat16 g_wolo[EMBED * EMBED];
__device__ __align__(16) __nv_bfloat16 g_w1hi[HID * EMBED];
__device__ __align__(16) __nv_bfloat16 g_w1lo[HID * EMBED];
__device__ __align__(16) __nv_bfloat16 g_qhi[(size_t)MTOT * EMBED];
__device__ __align__(16) __nv_bfloat16 g_qlo[(size_t)MTOT * EMBED];
__device__ __align__(16) __nv_bfloat16 g_cphi[BATCH * EMBED];
__device__ __align__(16) __nv_bfloat16 g_cplo[BATCH * EMBED];
__device__ __align__(16) __nv_bfloat16 g_cthi[BATCH * EMBED];
__device__ __align__(16) __nv_bfloat16 g_ctlo[BATCH * EMBED];
__device__ __align__(16) float g_h[BATCH * HID];

// ---------------- helpers ----------------
__device__ __forceinline__ void ffma2(unsigned long long& d,
                                      unsigned long long a,
                                      unsigned long long b) {
    asm("fma.rn.f32x2 %0, %1, %2, %0;" : "+l"(d) : "l"(a), "l"(b));
}
__device__ __forceinline__ unsigned long long packdup(float x) {
    unsigned long long r;
    asm("mov.b64 %0, {%1, %2};" : "=l"(r) : "f"(x), "f"(x));
    return r;
}
__device__ __forceinline__ unsigned long long pack2f(float a, float b) {
    unsigned long long r;
    asm("mov.b64 %0, {%1, %2};" : "=l"(r) : "f"(a), "f"(b));
    return r;
}
__device__ __forceinline__ float2 unpack2(unsigned long long v) {
    float2 r;
    asm("mov.b64 {%0, %1}, %2;" : "=f"(r.x), "=f"(r.y) : "l"(v));
    return r;
}
// fast exp: degree-5 Taylor of 2^f, rel err ~2.4e-6
__device__ __forceinline__ float fexp(float x) {
    x = fmaxf(x, -87.0f);
    float y = x * 1.4426950408889634f;
    int ir = __float2int_rn(y);
    float f = y - (float)ir;
    float p = 1.3333558146428443e-3f;
    p = fmaf(p, f, 9.618129107628477e-3f);
    p = fmaf(p, f, 5.55041086648216e-2f);
    p = fmaf(p, f, 2.402265069591007e-1f);
    p = fmaf(p, f, 6.931471805599453e-1f);
    p = fmaf(p, f, 1.0f);
    return p * __int_as_float((ir + 127) << 23);
}
__device__ __forceinline__ void mma16816(float* c, const uint32_t* a,
                                         const uint32_t* b) {
    asm volatile(
        "mma.sync.aligned.m16n8k16.row.col.f32.bf16.bf16.f32 "
        "{%0,%1,%2,%3}, {%4,%5,%6,%7}, {%8,%9}, {%0,%1,%2,%3};"
        : "+f"(c[0]), "+f"(c[1]), "+f"(c[2]), "+f"(c[3])
        : "r"(a[0]), "r"(a[1]), "r"(a[2]), "r"(a[3]), "r"(b[0]), "r"(b[1]));
}
__device__ __forceinline__ void ldsm4(uint32_t* r, uint32_t addr) {
    asm volatile("ldmatrix.sync.aligned.m8n8.x4.shared.b16 {%0,%1,%2,%3}, [%4];"
                 : "=r"(r[0]), "=r"(r[1]), "=r"(r[2]), "=r"(r[3]) : "r"(addr));
}
__device__ __forceinline__ void cp16(uint32_t dst_smem, const void* src) {
    asm volatile("cp.async.ca.shared.global [%0], [%1], 16;"
                 :: "r"(dst_smem), "l"(src));
}
__device__ __forceinline__ void cpcommit() { asm volatile("cp.async.commit_group;"); }
__device__ __forceinline__ void cpwait1()  { asm volatile("cp.async.wait_group 1;"); }
__device__ __forceinline__ void cpwait0()  { asm volatile("cp.async.wait_group 0;"); }

__device__ __forceinline__ void split_store2(__nv_bfloat16* Chi, __nv_bfloat16* Clo,
                                             size_t off, float v0, float v1) {
    __nv_bfloat16 h0 = __float2bfloat16(v0), h1 = __float2bfloat16(v1);
    __nv_bfloat16 l0 = __float2bfloat16(v0 - __bfloat162float(h0));
    __nv_bfloat16 l1 = __float2bfloat16(v1 - __bfloat162float(h1));
    __nv_bfloat162 H; H.x = h0; H.y = h1;
    __nv_bfloat162 L; L.x = l0; L.y = l1;
    *(__nv_bfloat162*)(Chi + off) = H;
    *(__nv_bfloat162*)(Clo + off) = L;
}

// ---------------------------------------------------------------------------
// K0: split a float matrix into hi/lo bf16 (generic)
// ---------------------------------------------------------------------------
__global__ __launch_bounds__(256) void wprep_kernel(
    const float* __restrict__ w, __nv_bfloat16* __restrict__ whi,
    __nv_bfloat16* __restrict__ wlo)
{
    int i = blockIdx.x * 256 + threadIdx.x;
    float v = w[i];
    __nv_bfloat16 h = __float2bfloat16(v);
    whi[i] = h;
    wlo[i] = __float2bfloat16(v - __bfloat162float(h));
}

// ---------------------------------------------------------------------------
// K1: one CTA per batch element: patchify -> emb GEMM (FFMA2) -> +pos -> hi/lo
// ---------------------------------------------------------------------------
__global__ __launch_bounds__(256) void seq_kernel(
    const float* __restrict__ x, const float* __restrict__ proj_w,
    const float* __restrict__ proj_b, const float* __restrict__ cls,
    const float* __restrict__ pos, __nv_bfloat16* __restrict__ shi_,
    __nv_bfloat16* __restrict__ slo_)
{
    __shared__ float ps[NPATCH * 49];
    __shared__ __align__(8) float wt[PFEAT * 66];

    const int b = blockIdx.x;
    const int t = threadIdx.x;
    const int tx = t & 31, ty = t >> 5;
    __nv_bfloat16* shi = shi_ + (size_t)b * SEQL * EMBED;
    __nv_bfloat16* slo = slo_ + (size_t)b * SEQL * EMBED;

    const float* xb = x + (size_t)b * 3 * 32 * 32;
    for (int idx = t; idx < NPATCH * PFEAT; idx += 256) {
        int n = idx / PFEAT, f = idx % PFEAT;
        int c = f >> 4, r4 = (f >> 2) & 3, c4 = f & 3;
        int py = n >> 3, px = n & 7;
        ps[n * 49 + f] = xb[c * 1024 + (py * 4 + r4) * 32 + (px * 4 + c4)];
    }
    for (int e = t; e < EMBED; e += 256) {
        float v = cls[e] + pos[e];
        __nv_bfloat16 h = __float2bfloat16(v);
        shi[e] = h; slo[e] = __float2bfloat16(v - __bfloat162float(h));
    }
    __syncthreads();

    for (int e0 = 0; e0 < EMBED; e0 += 64) {
        {
            int e = t >> 2, fc = (t & 3) * 12;
            const float4* src = (const float4*)(proj_w + (size_t)(e0 + e) * PFEAT + fc);
            #pragma unroll
            for (int j = 0; j < 3; j++) {
                float4 v = src[j];
                wt[(fc + j * 4 + 0) * 66 + e] = v.x;
                wt[(fc + j * 4 + 1) * 66 + e] = v.y;
                wt[(fc + j * 4 + 2) * 66 + e] = v.z;
                wt[(fc + j * 4 + 3) * 66 + e] = v.w;
            }
        }
        __syncthreads();
        int e1 = e0 + 2 * tx;
        unsigned long long acc2[8];
        {
            unsigned long long pb = pack2f(proj_b[e1], proj_b[e1 + 1]);
            #pragma unroll
            for (int i = 0; i < 8; i++) acc2[i] = pb;
        }
        #pragma unroll 4
        for (int f = 0; f < PFEAT; f++) {
            unsigned long long wv = *(const unsigned long long*)&wt[f * 66 + 2 * tx];
            #pragma unroll
            for (int i = 0; i < 8; i++)
                ffma2(acc2[i], packdup(ps[(ty + 8 * i) * 49 + f]), wv);
        }
        #pragma unroll
        for (int i = 0; i < 8; i++) {
            int n = ty + 8 * i;
            float2 av = unpack2(acc2[i]);
            float v0 = av.x + pos[(1 + n) * EMBED + e1];
            float v1 = av.y + pos[(1 + n) * EMBED + e1 + 1];
            __nv_bfloat16 h0 = __float2bfloat16(v0);
            __nv_bfloat16 h1 = __float2bfloat16(v1);
            shi[(1 + n) * EMBED + e1]     = h0;
            shi[(1 + n) * EMBED + e1 + 1] = h1;
            slo[(1 + n) * EMBED + e1]     = __float2bfloat16(v0 - __bfloat162float(h0));
            slo[(1 + n) * EMBED + e1 + 1] = __float2bfloat16(v1 - __bfloat162float(h1));
        }
        __syncthreads();
    }
}

// ---------------------------------------------------------------------------
// K2: generic 3-term bf16 MMA GEMM. C[M,N] = A[M,512] @ W[N,512]^T + bias.
// CTA 128x128, K chunk 32, 8 warps (4m x 2n), warp tile 32x64.
// mode 0: output bf16 hi/lo pair; mode 1: fp32 with exact GELU.
// ---------------------------------------------------------------------------
#define QSTR 40
#define NCH 16

__global__ __launch_bounds__(256, 2) void mma_gemm_kernel(
    const __nv_bfloat16* __restrict__ Ahi, const __nv_bfloat16* __restrict__ Alo,
    const __nv_bfloat16* __restrict__ Whi, const __nv_bfloat16* __restrict__ Wlo,
    const float* __restrict__ bias,
    __nv_bfloat16* __restrict__ Chi, __nv_bfloat16* __restrict__ Clo,
    float* __restrict__ Cf, int ldC, int mode)
{
    __shared__ __align__(16) __nv_bfloat16 sAh[2][128 * QSTR];
    __shared__ __align__(16) __nv_bfloat16 sAl[2][128 * QSTR];
    __shared__ __align__(16) __nv_bfloat16 sWh[2][128 * QSTR];
    __shared__ __align__(16) __nv_bfloat16 sWl[2][128 * QSTR];

    const int t = threadIdx.x;
    const int wid = t >> 5, lane = t & 31;
    const int gid = lane >> 2, tig = lane & 3;
    const int wm = wid & 3, wn = wid >> 2;
    const int m0 = blockIdx.y * 128, n0 = blockIdx.x * 128;

    float acc[2][8][4];
    #pragma unroll
    for (int i = 0; i < 2; i++)
        #pragma unroll
        for (int j = 0; j < 8; j++)
            #pragma unroll
            for (int k = 0; k < 4; k++) acc[i][j][k] = 0.f;

    const int r0 = t >> 2, kq = (t & 3) * 8;
    const uint32_t stg = 128 * QSTR * 2;
    const uint32_t rowB = 64 * QSTR * 2;
    const uint32_t bAh = (uint32_t)__cvta_generic_to_shared(&sAh[0][r0 * QSTR + kq]);
    const uint32_t bAl = (uint32_t)__cvta_generic_to_shared(&sAl[0][r0 * QSTR + kq]);
    const uint32_t bWh = (uint32_t)__cvta_generic_to_shared(&sWh[0][r0 * QSTR + kq]);
    const uint32_t bWl = (uint32_t)__cvta_generic_to_shared(&sWl[0][r0 * QSTR + kq]);

    auto issue = [&](int c, int s) {
        size_t ko = (size_t)c * 32 + kq;
        const uint32_t so = s * stg;
        cp16(bAh + so,        Ahi + (size_t)(m0 + r0) * EMBED + ko);
        cp16(bAh + so + rowB, Ahi + (size_t)(m0 + r0 + 64) * EMBED + ko);
        cp16(bAl + so,        Alo + (size_t)(m0 + r0) * EMBED + ko);
        cp16(bAl + so + rowB, Alo + (size_t)(m0 + r0 + 64) * EMBED + ko);
        cp16(bWh + so,        Whi + (size_t)(n0 + r0) * EMBED + ko);
        cp16(bWh + so + rowB, Whi + (size_t)(n0 + r0 + 64) * EMBED + ko);
        cp16(bWl + so,        Wlo + (size_t)(n0 + r0) * EMBED + ko);
        cp16(bWl + so + rowB, Wlo + (size_t)(n0 + r0 + 64) * EMBED + ko);
        cpcommit();
    };

    const int aoff = (wm * 32 + (lane & 15)) * QSTR + (lane >> 4) * 8;
    const int boffn = wn * 64 + ((lane >> 4) << 3) + (lane & 7);
    const int boffk = ((lane >> 3) & 1) * 8;

    const uint32_t baseAh = (uint32_t)__cvta_generic_to_shared(&sAh[0][0]);
    const uint32_t baseAl = (uint32_t)__cvta_generic_to_shared(&sAl[0][0]);
    const uint32_t baseWh = (uint32_t)__cvta_generic_to_shared(&sWh[0][0]);
    const uint32_t baseWl = (uint32_t)__cvta_generic_to_shared(&sWl[0][0]);

    issue(0, 0);
    for (int c = 0; c < NCH; c++) {
        const int s = c & 1;
        if (c + 1 < NCH) { issue(c + 1, (c + 1) & 1); cpwait1(); }
        else             { cpwait0(); }
        __syncthreads();
        const uint32_t so = s * stg;
        #pragma unroll
        for (int ks = 0; ks < 2; ks++) {
            const int k0 = ks * 16;
            uint32_t ah[2][4], al[2][4];
            #pragma unroll
            for (int mt = 0; mt < 2; mt++) {
                uint32_t ad = (uint32_t)((aoff + mt * 16 * QSTR + k0) * 2);
                ldsm4(ah[mt], baseAh + so + ad);
                ldsm4(al[mt], baseAl + so + ad);
            }
            #pragma unroll
            for (int p = 0; p < 4; p++) {
                uint32_t bh[4], bl[4];
                uint32_t bd = (uint32_t)(((boffn + p * 16) * QSTR + k0 + boffk) * 2);
                ldsm4(bh, baseWh + so + bd);
                ldsm4(bl, baseWl + so + bd);
                #pragma unroll
                for (int mt = 0; mt < 2; mt++) {
                    mma16816(acc[mt][2 * p],     ah[mt], bh);
                    mma16816(acc[mt][2 * p],     ah[mt], bl);
                    mma16816(acc[mt][2 * p],     al[mt], bh);
                    mma16816(acc[mt][2 * p + 1], ah[mt], bh + 2);
                    mma16816(acc[mt][2 * p + 1], ah[mt], bl + 2);
                    mma16816(acc[mt][2 * p + 1], al[mt], bh + 2);
                }
            }
        }
        __syncthreads();
    }

    #pragma unroll
    for (int mt = 0; mt < 2; mt++) {
        int r = m0 + wm * 32 + mt * 16 + gid;
        #pragma unroll
        for (int nt = 0; nt < 8; nt++) {
            int n = n0 + wn * 64 + nt * 8 + tig * 2;
            float b0 = bias[n], b1 = bias[n + 1];
            float v00 = acc[mt][nt][0] + b0, v01 = acc[mt][nt][1] + b1;
            float v10 = acc[mt][nt][2] + b0, v11 = acc[mt][nt][3] + b1;
            if (mode == 0) {
                split_store2(Chi, Clo, (size_t)r * ldC + n, v00, v01);
                split_store2(Chi, Clo, (size_t)(r + 8) * ldC + n, v10, v11);
            } else {
                v00 = 0.5f * v00 * (1.f + erff(v00 * 0.70710678118654752f));
                v01 = 0.5f * v01 * (1.f + erff(v01 * 0.70710678118654752f));
                v10 = 0.5f * v10 * (1.f + erff(v10 * 0.70710678118654752f));
                v11 = 0.5f * v11 * (1.f + erff(v11 * 0.70710678118654752f));
                Cf[(size_t)r * ldC + n]           = v00;
                Cf[(size_t)r * ldC + n + 1]       = v01;
                Cf[(size_t)(r + 8) * ldC + n]     = v10;
                Cf[(size_t)(r + 8) * ldC + n + 1] = v11;
            }
        }
    }
}

// ---------------------------------------------------------------------------
// K3: per (b,h): scores via bf16 mma (64x64) + scalar borders (R6 structure),
// col softmax (poly exp), att0 -> ct_pre (bf16 hi/lo)
// ---------------------------------------------------------------------------
#define ASTR 72

__global__ __launch_bounds__(128) void attn_kernel(
    const __nv_bfloat16* __restrict__ qhi, const __nv_bfloat16* __restrict__ qlo,
    __nv_bfloat16* __restrict__ cphi, __nv_bfloat16* __restrict__ cplo)
{
    __shared__ __align__(16) __nv_bfloat16 sQh[SEQL * ASTR];
    __shared__ __align__(16) __nv_bfloat16 sQl[SEQL * ASTR];
    __shared__ float sc[SEQL][68];
    __shared__ float w0s[68];

    const int b = blockIdx.y, h = blockIdx.x;
    const int t = threadIdx.x, lane = t & 31, wid = t >> 5;
    const int gid = lane >> 2, tig = lane & 3;
    const __nv_bfloat16* ph = qhi + (size_t)b * SEQL * EMBED + h * HDIM;
    const __nv_bfloat16* pl = qlo + (size_t)b * SEQL * EMBED + h * HDIM;

    for (int idx = t; idx < SEQL * 8; idx += 128) {
        int row = idx >> 3, c8 = (idx & 7) * 8;
        *(uint4*)(sQh + row * ASTR + c8) = *(const uint4*)(ph + (size_t)row * EMBED + c8);
        *(uint4*)(sQl + row * ASTR + c8) = *(const uint4*)(pl + (size_t)row * EMBED + c8);
    }
    __syncthreads();

    const uint32_t baseQh = (uint32_t)__cvta_generic_to_shared(&sQh[0]);
    const uint32_t baseQl = (uint32_t)__cvta_generic_to_shared(&sQl[0]);
    const int m0 = wid * 16;
    const int aoff = (m0 + (lane & 15)) * ASTR + (lane >> 4) * 8;
    const int boffn = ((lane >> 4) << 3) + (lane & 7);
    const int boffk = ((lane >> 3) & 1) * 8;

    float acc[8][4];
    #pragma unroll
    for (int j = 0; j < 8; j++)
        #pragma unroll
        for (int k = 0; k < 4; k++) acc[j][k] = 0.f;

    #pragma unroll
    for (int kc = 0; kc < 4; kc++) {
        const int k0 = kc * 16;
        uint32_t ah[4], al[4];
        ldsm4(ah, baseQh + (uint32_t)((aoff + k0) * 2));
        ldsm4(al, baseQl + (uint32_t)((aoff + k0) * 2));
        #pragma unroll
        for (int p = 0; p < 4; p++) {
            uint32_t bh[4], bl[4];
            uint32_t bd = (uint32_t)(((boffn + p * 16) * ASTR + k0 + boffk) * 2);
            ldsm4(bh, baseQh + bd);
            ldsm4(bl, baseQl + bd);
            mma16816(acc[2 * p],     ah, bh);
            mma16816(acc[2 * p],     ah, bl);
            mma16816(acc[2 * p],     al, bh);
            mma16816(acc[2 * p + 1], ah, bh + 2);
            mma16816(acc[2 * p + 1], ah, bl + 2);
            mma16816(acc[2 * p + 1], al, bh + 2);
        }
    }
    #pragma unroll
    for (int nt = 0; nt < 8; nt++) {
        int rr = m0 + gid, cc = nt * 8 + tig * 2;
        sc[rr][cc]         = acc[nt][0] * 0.125f;
        sc[rr][cc + 1]     = acc[nt][1] * 0.125f;
        sc[rr + 8][cc]     = acc[nt][2] * 0.125f;
        sc[rr + 8][cc + 1] = acc[nt][3] * 0.125f;
    }
    // row 64 (threads 63..127 -> cols 0..64), fp32 reconstructed on the fly
    if (t >= 63) {
        int tt = t - 63;
        float a = 0.f;
        #pragma unroll 4
        for (int k = 0; k < HDIM; k++) {
            float q64 = __bfloat162float(sQh[64 * ASTR + k]) +
                        __bfloat162float(sQl[64 * ASTR + k]);
            float qt  = __bfloat162float(sQh[tt * ASTR + k]) +
                        __bfloat162float(sQl[tt * ASTR + k]);
            a += q64 * qt;
        }
        sc[64][tt] = a * 0.125f;
    }
    __syncthreads();
    if (t < 64) sc[t][64] = sc[64][t];   // symmetry
    __syncthreads();

    if (t < SEQL) {
        float m = -1e30f;
        for (int s = 0; s < SEQL; s++) m = fmaxf(m, sc[s][t]);
        float Z = 0.f;
        for (int s = 0; s < SEQL; s++) Z += fexp(sc[s][t] - m);
        w0s[t] = fexp(sc[0][t] - m) / Z;
    }
    __syncthreads();

    if (t < HDIM) {
        float a = 0.f;
        for (int s = 0; s < SEQL; s++) {
            float qv = __bfloat162float(sQh[s * ASTR + t]) +
                       __bfloat162float(sQl[s * ASTR + t]);
            a += w0s[s] * qv;
        }
        size_t off = (size_t)b * EMBED + h * HDIM + t;
        __nv_bfloat16 hh = __float2bfloat16(a);
        cphi[off] = hh;
        cplo[off] = __float2bfloat16(a - __bfloat162float(hh));
    }
}

// logits: one CTA per batch row, one warp per class
__global__ __launch_bounds__(320) void logits_kernel(
    const float* __restrict__ h, const float* __restrict__ w2,
    const float* __restrict__ b2, float* __restrict__ out)
{
    int b = blockIdx.x;
    int lane = threadIdx.x & 31, w = threadIdx.x >> 5;
    const float* hb = h + (size_t)b * HID;
    float a = 0.f;
    for (int k = lane; k < HID; k += 32) a += hb[k] * w2[(size_t)w * HID + k];
    #pragma unroll
    for (int o = 16; o > 0; o >>= 1) a += __shfl_xor_sync(0xffffffffu, a, o);
    if (lane == 0) out[(size_t)b * NCLS + w] = a + b2[w];
}

extern "C" void kernel_launch(void* const* d_in, const int* in_sizes, int n_in,
                              void* d_out, int out_size)
{
    const float* x      = (const float*)d_in[0];
    const float* proj_w = (const float*)d_in[1];
    const float* proj_b = (const float*)d_in[2];
    const float* cls    = (const float*)d_in[3];
    const float* pos    = (const float*)d_in[4];
    const float* wq     = (const float*)d_in[5];
    const float* bq     = (const float*)d_in[6];
    const float* wo     = (const float*)d_in[7];
    const float* bo     = (const float*)d_in[8];
    const float* w1     = (const float*)d_in[9];
    const float* b1     = (const float*)d_in[10];
    const float* w2     = (const float*)d_in[11];
    const float* b2     = (const float*)d_in[12];
    float* out = (float*)d_out;

    __nv_bfloat16 *p_shi, *p_slo, *p_whi, *p_wlo, *p_wohi, *p_wolo;
    __nv_bfloat16 *p_w1hi, *p_w1lo, *p_qhi, *p_qlo, *p_cphi, *p_cplo, *p_cthi, *p_ctlo;
    float *p_h;
    cudaGetSymbolAddress((void**)&p_shi, g_shi);
    cudaGetSymbolAddress((void**)&p_slo, g_slo);
    cudaGetSymbolAddress((void**)&p_whi, g_whi);
    cudaGetSymbolAddress((void**)&p_wlo, g_wlo);
    cudaGetSymbolAddress((void**)&p_wohi, g_wohi);
    cudaGetSymbolAddress((void**)&p_wolo, g_wolo);
    cudaGetSymbolAddress((void**)&p_w1hi, g_w1hi);
    cudaGetSymbolAddress((void**)&p_w1lo, g_w1lo);
    cudaGetSymbolAddress((void**)&p_qhi, g_qhi);
    cudaGetSymbolAddress((void**)&p_qlo, g_qlo);
    cudaGetSymbolAddress((void**)&p_cphi, g_cphi);
    cudaGetSymbolAddress((void**)&p_cplo, g_cplo);
    cudaGetSymbolAddress((void**)&p_cthi, g_cthi);
    cudaGetSymbolAddress((void**)&p_ctlo, g_ctlo);
    cudaGetSymbolAddress((void**)&p_h, g_h);

    // launch order arranged so the 4th launch (ncu capture slot) is the q GEMM
    wprep_kernel<<<EMBED * EMBED / 256, 256>>>(wq, p_whi, p_wlo);            // 1
    seq_kernel<<<BATCH, 256>>>(x, proj_w, proj_b, cls, pos, p_shi, p_slo);   // 2
    wprep_kernel<<<EMBED * EMBED / 256, 256>>>(wo, p_wohi, p_wolo);          // 3
    mma_gemm_kernel<<<dim3(EMBED / 128, MTOT / 128), 256>>>(                 // 4
        p_shi, p_slo, p_whi, p_wlo, bq, p_qhi, p_qlo, nullptr, EMBED, 0);
    attn_kernel<<<dim3(HEADS, BATCH), 128>>>(p_qhi, p_qlo, p_cphi, p_cplo);  // 5
    wprep_kernel<<<HID * EMBED / 256, 256>>>(w1, p_w1hi, p_w1lo);            // 6
    mma_gemm_kernel<<<dim3(EMBED / 128, BATCH / 128), 256>>>(                // 7
        p_cphi, p_cplo, p_wohi, p_wolo, bo, p_cthi, p_ctlo, nullptr, EMBED, 0);
    mma_gemm_kernel<<<dim3(HID / 128, BATCH / 128), 256>>>(                  // 8
        p_cthi, p_ctlo, p_w1hi, p_w1lo, b1, nullptr, nullptr, p_h, HID, 1);
    logits_kernel<<<BATCH, 320>>>(p_h, w2, b2, out);                         // 9
}

// round 9
// speedup vs baseline: 1.7983x; 1.6557x over previous
#include <cuda_runtime.h>
#include <cuda_fp16.h>
#include <math.h>
#include <stdint.h>

#define EMBED 512
#define HEADS 8
#define HDIM 64
#define SEQL 65
#define NPATCH 64
#define PFEAT 48
#define HID 1024
#define NCLS 10
#define BATCH 2048
#define MTOT (BATCH * SEQL)   // 133120

// global scratch (no allocations allowed)
__device__ __align__(16) __half g_s16[(size_t)MTOT * EMBED];
__device__ __align__(16) __half g_wq16[EMBED * EMBED];
__device__ __align__(16) __half g_wo16[EMBED * EMBED];
__device__ __align__(16) __half g_w116[HID * EMBED];
__device__ __align__(16) __half g_q16[(size_t)MTOT * EMBED];
__device__ __align__(16) __half g_cp16[BATCH * EMBED];
__device__ __align__(16) __half g_ct16[BATCH * EMBED];
__device__ __align__(16) float g_h[BATCH * HID];

// ---------------- helpers ----------------
__device__ __forceinline__ void ffma2(unsigned long long& d,
                                      unsigned long long a,
                                      unsigned long long b) {
    asm("fma.rn.f32x2 %0, %1, %2, %0;" : "+l"(d) : "l"(a), "l"(b));
}
__device__ __forceinline__ unsigned long long packdup(float x) {
    unsigned long long r;
    asm("mov.b64 %0, {%1, %2};" : "=l"(r) : "f"(x), "f"(x));
    return r;
}
__device__ __forceinline__ unsigned long long pack2f(float a, float b) {
    unsigned long long r;
    asm("mov.b64 %0, {%1, %2};" : "=l"(r) : "f"(a), "f"(b));
    return r;
}
__device__ __forceinline__ float2 unpack2(unsigned long long v) {
    float2 r;
    asm("mov.b64 {%0, %1}, %2;" : "=f"(r.x), "=f"(r.y) : "l"(v));
    return r;
}
// fast exp: degree-5 Taylor of 2^f, rel err ~2.4e-6
__device__ __forceinline__ float fexp(float x) {
    x = fmaxf(x, -87.0f);
    float y = x * 1.4426950408889634f;
    int ir = __float2int_rn(y);
    float f = y - (float)ir;
    float p = 1.3333558146428443e-3f;
    p = fmaf(p, f, 9.618129107628477e-3f);
    p = fmaf(p, f, 5.55041086648216e-2f);
    p = fmaf(p, f, 2.402265069591007e-1f);
    p = fmaf(p, f, 6.931471805599453e-1f);
    p = fmaf(p, f, 1.0f);
    return p * __int_as_float((ir + 127) << 23);
}
// fp16 x fp16 -> fp32 accum MMA
__device__ __forceinline__ void mma16816h(float* c, const uint32_t* a,
                                          const uint32_t* b) {
    asm volatile(
        "mma.sync.aligned.m16n8k16.row.col.f32.f16.f16.f32 "
        "{%0,%1,%2,%3}, {%4,%5,%6,%7}, {%8,%9}, {%0,%1,%2,%3};"
        : "+f"(c[0]), "+f"(c[1]), "+f"(c[2]), "+f"(c[3])
        : "r"(a[0]), "r"(a[1]), "r"(a[2]), "r"(a[3]), "r"(b[0]), "r"(b[1]));
}
__device__ __forceinline__ void ldsm4(uint32_t* r, uint32_t addr) {
    asm volatile("ldmatrix.sync.aligned.m8n8.x4.shared.b16 {%0,%1,%2,%3}, [%4];"
                 : "=r"(r[0]), "=r"(r[1]), "=r"(r[2]), "=r"(r[3]) : "r"(addr));
}
__device__ __forceinline__ void cp16(uint32_t dst_smem, const void* src) {
    asm volatile("cp.async.ca.shared.global [%0], [%1], 16;"
                 :: "r"(dst_smem), "l"(src));
}
__device__ __forceinline__ void cpcommit() { asm volatile("cp.async.commit_group;"); }
__device__ __forceinline__ void cpwait1()  { asm volatile("cp.async.wait_group 1;"); }
__device__ __forceinline__ void cpwait0()  { asm volatile("cp.async.wait_group 0;"); }

// ---------------------------------------------------------------------------
// K0: convert float matrix to fp16
// ---------------------------------------------------------------------------
__global__ __launch_bounds__(256) void wprep_kernel(
    const float* __restrict__ w, __half* __restrict__ w16)
{
    int i = blockIdx.x * 256 + threadIdx.x;
    w16[i] = __float2half(w[i]);
}

// ---------------------------------------------------------------------------
// K1: one CTA per batch element: patchify -> emb GEMM (FFMA2) -> +pos -> fp16
// ---------------------------------------------------------------------------
__global__ __launch_bounds__(256) void seq_kernel(
    const float* __restrict__ x, const float* __restrict__ proj_w,
    const float* __restrict__ proj_b, const float* __restrict__ cls,
    const float* __restrict__ pos, __half* __restrict__ s16_)
{
    __shared__ float ps[NPATCH * 49];
    __shared__ __align__(8) float wt[PFEAT * 66];

    const int b = blockIdx.x;
    const int t = threadIdx.x;
    const int tx = t & 31, ty = t >> 5;
    __half* sb = s16_ + (size_t)b * SEQL * EMBED;

    const float* xb = x + (size_t)b * 3 * 32 * 32;
    for (int idx = t; idx < NPATCH * PFEAT; idx += 256) {
        int n = idx / PFEAT, f = idx % PFEAT;
        int c = f >> 4, r4 = (f >> 2) & 3, c4 = f & 3;
        int py = n >> 3, px = n & 7;
        ps[n * 49 + f] = xb[c * 1024 + (py * 4 + r4) * 32 + (px * 4 + c4)];
    }
    for (int e = t; e < EMBED; e += 256)
        sb[e] = __float2half(cls[e] + pos[e]);
    __syncthreads();

    for (int e0 = 0; e0 < EMBED; e0 += 64) {
        {
            int e = t >> 2, fc = (t & 3) * 12;
            const float4* src = (const float4*)(proj_w + (size_t)(e0 + e) * PFEAT + fc);
            #pragma unroll
            for (int j = 0; j < 3; j++) {
                float4 v = src[j];
                wt[(fc + j * 4 + 0) * 66 + e] = v.x;
                wt[(fc + j * 4 + 1) * 66 + e] = v.y;
                wt[(fc + j * 4 + 2) * 66 + e] = v.z;
                wt[(fc + j * 4 + 3) * 66 + e] = v.w;
            }
        }
        __syncthreads();
        int e1 = e0 + 2 * tx;
        unsigned long long acc2[8];
        {
            unsigned long long pb = pack2f(proj_b[e1], proj_b[e1 + 1]);
            #pragma unroll
            for (int i = 0; i < 8; i++) acc2[i] = pb;
        }
        #pragma unroll 4
        for (int f = 0; f < PFEAT; f++) {
            unsigned long long wv = *(const unsigned long long*)&wt[f * 66 + 2 * tx];
            #pragma unroll
            for (int i = 0; i < 8; i++)
                ffma2(acc2[i], packdup(ps[(ty + 8 * i) * 49 + f]), wv);
        }
        #pragma unroll
        for (int i = 0; i < 8; i++) {
            int n = ty + 8 * i;
            float2 av = unpack2(acc2[i]);
            __half2 H;
            H.x = __float2half(av.x + pos[(1 + n) * EMBED + e1]);
            H.y = __float2half(av.y + pos[(1 + n) * EMBED + e1 + 1]);
            *(__half2*)(sb + (1 + n) * EMBED + e1) = H;
        }
        __syncthreads();
    }
}

// ---------------------------------------------------------------------------
// K2: generic fp16 MMA GEMM. C[M,N] = A[M,512] @ W[N,512]^T + bias.
// CTA 128x128, K chunk 32, 8 warps (4m x 2n), warp tile 32x64.
// mode 0: output fp16; mode 1: fp32 with exact GELU.
// ---------------------------------------------------------------------------
#define QSTR 40
#define NCH 16

__global__ __launch_bounds__(256, 2) void mma_gemm_kernel(
    const __half* __restrict__ A, const __half* __restrict__ W,
    const float* __restrict__ bias,
    __half* __restrict__ Ch, float* __restrict__ Cf, int ldC, int mode)
{
    __shared__ __align__(16) __half sA[2][128 * QSTR];
    __shared__ __align__(16) __half sW[2][128 * QSTR];

    const int t = threadIdx.x;
    const int wid = t >> 5, lane = t & 31;
    const int gid = lane >> 2, tig = lane & 3;
    const int wm = wid & 3, wn = wid >> 2;
    const int m0 = blockIdx.y * 128, n0 = blockIdx.x * 128;

    float acc[2][8][4];
    #pragma unroll
    for (int i = 0; i < 2; i++)
        #pragma unroll
        for (int j = 0; j < 8; j++)
            #pragma unroll
            for (int k = 0; k < 4; k++) acc[i][j][k] = 0.f;

    const int r0 = t >> 2, kq = (t & 3) * 8;
    const uint32_t stg = 128 * QSTR * 2;
    const uint32_t rowB = 64 * QSTR * 2;
    const uint32_t bA = (uint32_t)__cvta_generic_to_shared(&sA[0][r0 * QSTR + kq]);
    const uint32_t bW = (uint32_t)__cvta_generic_to_shared(&sW[0][r0 * QSTR + kq]);

    auto issue = [&](int c, int s) {
        size_t ko = (size_t)c * 32 + kq;
        const uint32_t so = s * stg;
        cp16(bA + so,        A + (size_t)(m0 + r0) * EMBED + ko);
        cp16(bA + so + rowB, A + (size_t)(m0 + r0 + 64) * EMBED + ko);
        cp16(bW + so,        W + (size_t)(n0 + r0) * EMBED + ko);
        cp16(bW + so + rowB, W + (size_t)(n0 + r0 + 64) * EMBED + ko);
        cpcommit();
    };

    const int aoff = (wm * 32 + (lane & 15)) * QSTR + (lane >> 4) * 8;
    const int boffn = wn * 64 + ((lane >> 4) << 3) + (lane & 7);
    const int boffk = ((lane >> 3) & 1) * 8;

    const uint32_t baseA = (uint32_t)__cvta_generic_to_shared(&sA[0][0]);
    const uint32_t baseW = (uint32_t)__cvta_generic_to_shared(&sW[0][0]);

    issue(0, 0);
    for (int c = 0; c < NCH; c++) {
        const int s = c & 1;
        if (c + 1 < NCH) { issue(c + 1, (c + 1) & 1); cpwait1(); }
        else             { cpwait0(); }
        __syncthreads();
        const uint32_t so = s * stg;
        #pragma unroll
        for (int ks = 0; ks < 2; ks++) {
            const int k0 = ks * 16;
            uint32_t ah[2][4];
            #pragma unroll
            for (int mt = 0; mt < 2; mt++)
                ldsm4(ah[mt], baseA + so + (uint32_t)((aoff + mt * 16 * QSTR + k0) * 2));
            #pragma unroll
            for (int p = 0; p < 4; p++) {
                uint32_t bb[4];
                ldsm4(bb, baseW + so + (uint32_t)(((boffn + p * 16) * QSTR + k0 + boffk) * 2));
                #pragma unroll
                for (int mt = 0; mt < 2; mt++) {
                    mma16816h(acc[mt][2 * p],     ah[mt], bb);
                    mma16816h(acc[mt][2 * p + 1], ah[mt], bb + 2);
                }
            }
        }
        __syncthreads();
    }

    #pragma unroll
    for (int mt = 0; mt < 2; mt++) {
        int r = m0 + wm * 32 + mt * 16 + gid;
        #pragma unroll
        for (int nt = 0; nt < 8; nt++) {
            int n = n0 + wn * 64 + nt * 8 + tig * 2;
            float b0 = bias[n], b1 = bias[n + 1];
            float v00 = acc[mt][nt][0] + b0, v01 = acc[mt][nt][1] + b1;
            float v10 = acc[mt][nt][2] + b0, v11 = acc[mt][nt][3] + b1;
            if (mode == 0) {
                __half2 H0; H0.x = __float2half(v00); H0.y = __float2half(v01);
                __half2 H1; H1.x = __float2half(v10); H1.y = __float2half(v11);
                *(__half2*)(Ch + (size_t)r * ldC + n)       = H0;
                *(__half2*)(Ch + (size_t)(r + 8) * ldC + n) = H1;
            } else {
                v00 = 0.5f * v00 * (1.f + erff(v00 * 0.70710678118654752f));
                v01 = 0.5f * v01 * (1.f + erff(v01 * 0.70710678118654752f));
                v10 = 0.5f * v10 * (1.f + erff(v10 * 0.70710678118654752f));
                v11 = 0.5f * v11 * (1.f + erff(v11 * 0.70710678118654752f));
                Cf[(size_t)r * ldC + n]           = v00;
                Cf[(size_t)r * ldC + n + 1]       = v01;
                Cf[(size_t)(r + 8) * ldC + n]     = v10;
                Cf[(size_t)(r + 8) * ldC + n + 1] = v11;
            }
        }
    }
}

// ---------------------------------------------------------------------------
// K3: per (b,h): scores via fp16 mma (64x64) + scalar borders,
// col softmax (poly exp), att0 -> ct_pre fp16
// ---------------------------------------------------------------------------
#define ASTR 72

__global__ __launch_bounds__(128) void attn_kernel(
    const __half* __restrict__ q16, __half* __restrict__ cp16o)
{
    __shared__ __align__(16) __half sQ[SEQL * ASTR];
    __shared__ float sc[SEQL][68];
    __shared__ float w0s[68];

    const int b = blockIdx.y, h = blockIdx.x;
    const int t = threadIdx.x, lane = t & 31, wid = t >> 5;
    const int gid = lane >> 2, tig = lane & 3;
    const __half* pq = q16 + (size_t)b * SEQL * EMBED + h * HDIM;

    for (int idx = t; idx < SEQL * 8; idx += 128) {
        int row = idx >> 3, c8 = (idx & 7) * 8;
        *(uint4*)(sQ + row * ASTR + c8) = *(const uint4*)(pq + (size_t)row * EMBED + c8);
    }
    __syncthreads();

    const uint32_t baseQ = (uint32_t)__cvta_generic_to_shared(&sQ[0]);
    const int m0 = wid * 16;
    const int aoff = (m0 + (lane & 15)) * ASTR + (lane >> 4) * 8;
    const int boffn = ((lane >> 4) << 3) + (lane & 7);
    const int boffk = ((lane >> 3) & 1) * 8;

    float acc[8][4];
    #pragma unroll
    for (int j = 0; j < 8; j++)
        #pragma unroll
        for (int k = 0; k < 4; k++) acc[j][k] = 0.f;

    #pragma unroll
    for (int kc = 0; kc < 4; kc++) {
        const int k0 = kc * 16;
        uint32_t ah[4];
        ldsm4(ah, baseQ + (uint32_t)((aoff + k0) * 2));
        #pragma unroll
        for (int p = 0; p < 4; p++) {
            uint32_t bb[4];
            ldsm4(bb, baseQ + (uint32_t)(((boffn + p * 16) * ASTR + k0 + boffk) * 2));
            mma16816h(acc[2 * p],     ah, bb);
            mma16816h(acc[2 * p + 1], ah, bb + 2);
        }
    }
    #pragma unroll
    for (int nt = 0; nt < 8; nt++) {
        int rr = m0 + gid, cc = nt * 8 + tig * 2;
        sc[rr][cc]         = acc[nt][0] * 0.125f;
        sc[rr][cc + 1]     = acc[nt][1] * 0.125f;
        sc[rr + 8][cc]     = acc[nt][2] * 0.125f;
        sc[rr + 8][cc + 1] = acc[nt][3] * 0.125f;
    }
    // row 64 (threads 63..127 -> cols 0..64)
    if (t >= 63) {
        int tt = t - 63;
        float a = 0.f;
        #pragma unroll 8
        for (int k = 0; k < HDIM; k++)
            a += __half2float(sQ[64 * ASTR + k]) * __half2float(sQ[tt * ASTR + k]);
        sc[64][tt] = a * 0.125f;
    }
    __syncthreads();
    if (t < 64) sc[t][64] = sc[64][t];   // symmetry
    __syncthreads();

    if (t < SEQL) {
        float m = -1e30f;
        for (int s = 0; s < SEQL; s++) m = fmaxf(m, sc[s][t]);
        float Z = 0.f;
        for (int s = 0; s < SEQL; s++) Z += fexp(sc[s][t] - m);
        w0s[t] = fexp(sc[0][t] - m) / Z;
    }
    __syncthreads();

    if (t < HDIM) {
        float a = 0.f;
        for (int s = 0; s < SEQL; s++)
            a += w0s[s] * __half2float(sQ[s * ASTR + t]);
        cp16o[(size_t)b * EMBED + h * HDIM + t] = __float2half(a);
    }
}

// logits: one CTA per batch row, one warp per class
__global__ __launch_bounds__(320) void logits_kernel(
    const float* __restrict__ h, const float* __restrict__ w2,
    const float* __restrict__ b2, float* __restrict__ out)
{
    int b = blockIdx.x;
    int lane = threadIdx.x & 31, w = threadIdx.x >> 5;
    const float* hb = h + (size_t)b * HID;
    float a = 0.f;
    for (int k = lane; k < HID; k += 32) a += hb[k] * w2[(size_t)w * HID + k];
    #pragma unroll
    for (int o = 16; o > 0; o >>= 1) a += __shfl_xor_sync(0xffffffffu, a, o);
    if (lane == 0) out[(size_t)b * NCLS + w] = a + b2[w];
}

extern "C" void kernel_launch(void* const* d_in, const int* in_sizes, int n_in,
                              void* d_out, int out_size)
{
    const float* x      = (const float*)d_in[0];
    const float* proj_w = (const float*)d_in[1];
    const float* proj_b = (const float*)d_in[2];
    const float* cls    = (const float*)d_in[3];
    const float* pos    = (const float*)d_in[4];
    const float* wq     = (const float*)d_in[5];
    const float* bq     = (const float*)d_in[6];
    const float* wo     = (const float*)d_in[7];
    const float* bo     = (const float*)d_in[8];
    const float* w1     = (const float*)d_in[9];
    const float* b1     = (const float*)d_in[10];
    const float* w2     = (const float*)d_in[11];
    const float* b2     = (const float*)d_in[12];
    float* out = (float*)d_out;

    __half *p_s, *p_wq, *p_wo, *p_w1, *p_q, *p_cp, *p_ct;
    float *p_h;
    cudaGetSymbolAddress((void**)&p_s, g_s16);
    cudaGetSymbolAddress((void**)&p_wq, g_wq16);
    cudaGetSymbolAddress((void**)&p_wo, g_wo16);
    cudaGetSymbolAddress((void**)&p_w1, g_w116);
    cudaGetSymbolAddress((void**)&p_q, g_q16);
    cudaGetSymbolAddress((void**)&p_cp, g_cp16);
    cudaGetSymbolAddress((void**)&p_ct, g_ct16);
    cudaGetSymbolAddress((void**)&p_h, g_h);

    // launch order keeps the q GEMM in ncu capture slot 4
    wprep_kernel<<<EMBED * EMBED / 256, 256>>>(wq, p_wq);                    // 1
    seq_kernel<<<BATCH, 256>>>(x, proj_w, proj_b, cls, pos, p_s);            // 2
    wprep_kernel<<<EMBED * EMBED / 256, 256>>>(wo, p_wo);                    // 3
    mma_gemm_kernel<<<dim3(EMBED / 128, MTOT / 128), 256>>>(                 // 4
        p_s, p_wq, bq, p_q, nullptr, EMBED, 0);
    attn_kernel<<<dim3(HEADS, BATCH), 128>>>(p_q, p_cp);                     // 5
    wprep_kernel<<<HID * EMBED / 256, 256>>>(w1, p_w1);                      // 6
    mma_gemm_kernel<<<dim3(EMBED / 128, BATCH / 128), 256>>>(                // 7
        p_cp, p_wo, bo, p_ct, nullptr, EMBED, 0);
    mma_gemm_kernel<<<dim3(HID / 128, BATCH / 128), 256>>>(                  // 8
        p_ct, p_w1, b1, nullptr, p_h, HID, 1);
    logits_kernel<<<BATCH, 320>>>(p_h, w2, b2, out);                         // 9
}

// round 10
// speedup vs baseline: 1.9506x; 1.0847x over previous
#include <cuda_runtime.h>
#include <cuda_fp16.h>
#include <math.h>
#include <stdint.h>

#define EMBED 512
#define HEADS 8
#define HDIM 64
#define SEQL 65
#define NPATCH 64
#define PFEAT 48
#define HID 1024
#define NCLS 10
#define BATCH 2048
#define MTOT (BATCH * SEQL)   // 133120

// global scratch (no allocations allowed)
__device__ __align__(16) __half g_s16[(size_t)MTOT * EMBED];
__device__ __align__(16) __half g_wq16[EMBED * EMBED];
__device__ __align__(16) __half g_wo16[EMBED * EMBED];
__device__ __align__(16) __half g_w116[HID * EMBED];
__device__ __align__(16) __half g_q16[(size_t)MTOT * EMBED];
__device__ __align__(16) __half g_cp16[BATCH * EMBED];
__device__ __align__(16) __half g_ct16[BATCH * EMBED];
__device__ __align__(16) float g_h[BATCH * HID];

// ---------------- helpers ----------------
__device__ __forceinline__ void ffma2(unsigned long long& d,
                                      unsigned long long a,
                                      unsigned long long b) {
    asm("fma.rn.f32x2 %0, %1, %2, %0;" : "+l"(d) : "l"(a), "l"(b));
}
__device__ __forceinline__ unsigned long long packdup(float x) {
    unsigned long long r;
    asm("mov.b64 %0, {%1, %2};" : "=l"(r) : "f"(x), "f"(x));
    return r;
}
__device__ __forceinline__ unsigned long long pack2f(float a, float b) {
    unsigned long long r;
    asm("mov.b64 %0, {%1, %2};" : "=l"(r) : "f"(a), "f"(b));
    return r;
}
__device__ __forceinline__ float2 unpack2(unsigned long long v) {
    float2 r;
    asm("mov.b64 {%0, %1}, %2;" : "=f"(r.x), "=f"(r.y) : "l"(v));
    return r;
}
// fast exp: degree-5 Taylor of 2^f, rel err ~2.4e-6
__device__ __forceinline__ float fexp(float x) {
    x = fmaxf(x, -87.0f);
    float y = x * 1.4426950408889634f;
    int ir = __float2int_rn(y);
    float f = y - (float)ir;
    float p = 1.3333558146428443e-3f;
    p = fmaf(p, f, 9.618129107628477e-3f);
    p = fmaf(p, f, 5.55041086648216e-2f);
    p = fmaf(p, f, 2.402265069591007e-1f);
    p = fmaf(p, f, 6.931471805599453e-1f);
    p = fmaf(p, f, 1.0f);
    return p * __int_as_float((ir + 127) << 23);
}
// fp16 x fp16 -> fp32 accum MMA
__device__ __forceinline__ void mma16816h(float* c, const uint32_t* a,
                                          const uint32_t* b) {
    asm volatile(
        "mma.sync.aligned.m16n8k16.row.col.f32.f16.f16.f32 "
        "{%0,%1,%2,%3}, {%4,%5,%6,%7}, {%8,%9}, {%0,%1,%2,%3};"
        : "+f"(c[0]), "+f"(c[1]), "+f"(c[2]), "+f"(c[3])
        : "r"(a[0]), "r"(a[1]), "r"(a[2]), "r"(a[3]), "r"(b[0]), "r"(b[1]));
}
__device__ __forceinline__ void ldsm4(uint32_t* r, uint32_t addr) {
    asm volatile("ldmatrix.sync.aligned.m8n8.x4.shared.b16 {%0,%1,%2,%3}, [%4];"
                 : "=r"(r[0]), "=r"(r[1]), "=r"(r[2]), "=r"(r[3]) : "r"(addr));
}
__device__ __forceinline__ void cp16(uint32_t dst_smem, const void* src) {
    asm volatile("cp.async.ca.shared.global [%0], [%1], 16;"
                 :: "r"(dst_smem), "l"(src));
}
__device__ __forceinline__ void cpcommit() { asm volatile("cp.async.commit_group;"); }
__device__ __forceinline__ void cpwait0()  { asm volatile("cp.async.wait_group 0;"); }

// ---------------------------------------------------------------------------
// K0: convert float matrix to fp16
// ---------------------------------------------------------------------------
__global__ __launch_bounds__(256) void wprep_kernel(
    const float* __restrict__ w, __half* __restrict__ w16)
{
    int i = blockIdx.x * 256 + threadIdx.x;
    w16[i] = __float2half(w[i]);
}

// ---------------------------------------------------------------------------
// K1: one CTA per batch element: patchify -> emb GEMM (FFMA2) -> +pos -> fp16
// ---------------------------------------------------------------------------
__global__ __launch_bounds__(256) void seq_kernel(
    const float* __restrict__ x, const float* __restrict__ proj_w,
    const float* __restrict__ proj_b, const float* __restrict__ cls,
    const float* __restrict__ pos, __half* __restrict__ s16_)
{
    __shared__ float ps[NPATCH * 49];
    __shared__ __align__(8) float wt[PFEAT * 66];

    const int b = blockIdx.x;
    const int t = threadIdx.x;
    const int tx = t & 31, ty = t >> 5;
    __half* sb = s16_ + (size_t)b * SEQL * EMBED;

    const float* xb = x + (size_t)b * 3 * 32 * 32;
    for (int idx = t; idx < NPATCH * PFEAT; idx += 256) {
        int n = idx / PFEAT, f = idx % PFEAT;
        int c = f >> 4, r4 = (f >> 2) & 3, c4 = f & 3;
        int py = n >> 3, px = n & 7;
        ps[n * 49 + f] = xb[c * 1024 + (py * 4 + r4) * 32 + (px * 4 + c4)];
    }
    for (int e = t; e < EMBED; e += 256)
        sb[e] = __float2half(cls[e] + pos[e]);
    __syncthreads();

    for (int e0 = 0; e0 < EMBED; e0 += 64) {
        {
            int e = t >> 2, fc = (t & 3) * 12;
            const float4* src = (const float4*)(proj_w + (size_t)(e0 + e) * PFEAT + fc);
            #pragma unroll
            for (int j = 0; j < 3; j++) {
                float4 v = src[j];
                wt[(fc + j * 4 + 0) * 66 + e] = v.x;
                wt[(fc + j * 4 + 1) * 66 + e] = v.y;
                wt[(fc + j * 4 + 2) * 66 + e] = v.z;
                wt[(fc + j * 4 + 3) * 66 + e] = v.w;
            }
        }
        __syncthreads();
        int e1 = e0 + 2 * tx;
        unsigned long long acc2[8];
        {
            unsigned long long pb = pack2f(proj_b[e1], proj_b[e1 + 1]);
            #pragma unroll
            for (int i = 0; i < 8; i++) acc2[i] = pb;
        }
        #pragma unroll 4
        for (int f = 0; f < PFEAT; f++) {
            unsigned long long wv = *(const unsigned long long*)&wt[f * 66 + 2 * tx];
            #pragma unroll
            for (int i = 0; i < 8; i++)
                ffma2(acc2[i], packdup(ps[(ty + 8 * i) * 49 + f]), wv);
        }
        #pragma unroll
        for (int i = 0; i < 8; i++) {
            int n = ty + 8 * i;
            float2 av = unpack2(acc2[i]);
            __half2 H;
            H.x = __float2half(av.x + pos[(1 + n) * EMBED + e1]);
            H.y = __float2half(av.y + pos[(1 + n) * EMBED + e1 + 1]);
            *(__half2*)(sb + (1 + n) * EMBED + e1) = H;
        }
        __syncthreads();
    }
}

// ---------------------------------------------------------------------------
// K2: fp16 MMA GEMM, K-chunk 64, double buffer, ONE barrier per chunk.
// CTA 128x128, 8 warps (4m x 2n), warp tile 32x64.
// mode 0: output fp16; mode 1: fp32 with exact GELU.
// ---------------------------------------------------------------------------
#define QSTR 72   // half row stride (144B: ldmatrix conflict-free)
#define KC 64
#define NCHK (EMBED / KC)   // 8

__global__ __launch_bounds__(256, 2) void mma_gemm_kernel(
    const __half* __restrict__ A, const __half* __restrict__ W,
    const float* __restrict__ bias,
    __half* __restrict__ Ch, float* __restrict__ Cf, int ldC, int mode)
{
    __shared__ __align__(16) __half sA[2][128 * QSTR];
    __shared__ __align__(16) __half sW[2][128 * QSTR];

    const int t = threadIdx.x;
    const int wid = t >> 5, lane = t & 31;
    const int gid = lane >> 2, tig = lane & 3;
    const int wm = wid & 3, wn = wid >> 2;
    const int m0 = blockIdx.y * 128, n0 = blockIdx.x * 128;

    float acc[2][8][4];
    #pragma unroll
    for (int i = 0; i < 2; i++)
        #pragma unroll
        for (int j = 0; j < 8; j++)
            #pragma unroll
            for (int k = 0; k < 4; k++) acc[i][j][k] = 0.f;

    const uint32_t stg = 128 * QSTR * 2;   // bytes per stage
    const uint32_t baseA = (uint32_t)__cvta_generic_to_shared(&sA[0][0]);
    const uint32_t baseW = (uint32_t)__cvta_generic_to_shared(&sW[0][0]);

    const int crow = t >> 3, ccol = (t & 7) * 8;   // cp.async thread mapping
    auto issue = [&](int c, int s) {
        const uint32_t so = s * stg;
        const size_t ko = (size_t)c * KC + ccol;
        #pragma unroll
        for (int j = 0; j < 4; j++) {
            int row = crow + j * 32;
            uint32_t d = (uint32_t)((row * QSTR + ccol) * 2);
            cp16(baseA + so + d, A + (size_t)(m0 + row) * EMBED + ko);
            cp16(baseW + so + d, W + (size_t)(n0 + row) * EMBED + ko);
        }
        cpcommit();
    };

    const int aoff = (wm * 32 + (lane & 15)) * QSTR + (lane >> 4) * 8;
    const int boffn = wn * 64 + ((lane >> 4) << 3) + (lane & 7);
    const int boffk = ((lane >> 3) & 1) * 8;

    issue(0, 0);
    for (int c = 0; c < NCHK; c++) {
        const int s = c & 1;
        cpwait0();          // own copies of chunk c landed
        __syncthreads();    // all copies visible; all compute(c-1) done
        if (c + 1 < NCHK) issue(c + 1, s ^ 1);   // overwrite the other stage
        const uint32_t so = s * stg;
        #pragma unroll
        for (int ks = 0; ks < 4; ks++) {
            const int k0 = ks * 16;
            uint32_t ah[2][4];
            #pragma unroll
            for (int mt = 0; mt < 2; mt++)
                ldsm4(ah[mt], baseA + so + (uint32_t)((aoff + mt * 16 * QSTR + k0) * 2));
            #pragma unroll
            for (int p = 0; p < 4; p++) {
                uint32_t bb[4];
                ldsm4(bb, baseW + so + (uint32_t)(((boffn + p * 16) * QSTR + k0 + boffk) * 2));
                #pragma unroll
                for (int mt = 0; mt < 2; mt++) {
                    mma16816h(acc[mt][2 * p],     ah[mt], bb);
                    mma16816h(acc[mt][2 * p + 1], ah[mt], bb + 2);
                }
            }
        }
    }

    __syncthreads();
    #pragma unroll
    for (int mt = 0; mt < 2; mt++) {
        int r = m0 + wm * 32 + mt * 16 + gid;
        #pragma unroll
        for (int nt = 0; nt < 8; nt++) {
            int n = n0 + wn * 64 + nt * 8 + tig * 2;
            float b0 = bias[n], b1 = bias[n + 1];
            float v00 = acc[mt][nt][0] + b0, v01 = acc[mt][nt][1] + b1;
            float v10 = acc[mt][nt][2] + b0, v11 = acc[mt][nt][3] + b1;
            if (mode == 0) {
                __half2 H0; H0.x = __float2half(v00); H0.y = __float2half(v01);
                __half2 H1; H1.x = __float2half(v10); H1.y = __float2half(v11);
                *(__half2*)(Ch + (size_t)r * ldC + n)       = H0;
                *(__half2*)(Ch + (size_t)(r + 8) * ldC + n) = H1;
            } else {
                v00 = 0.5f * v00 * (1.f + erff(v00 * 0.70710678118654752f));
                v01 = 0.5f * v01 * (1.f + erff(v01 * 0.70710678118654752f));
                v10 = 0.5f * v10 * (1.f + erff(v10 * 0.70710678118654752f));
                v11 = 0.5f * v11 * (1.f + erff(v11 * 0.70710678118654752f));
                Cf[(size_t)r * ldC + n]           = v00;
                Cf[(size_t)r * ldC + n + 1]       = v01;
                Cf[(size_t)(r + 8) * ldC + n]     = v10;
                Cf[(size_t)(r + 8) * ldC + n + 1] = v11;
            }
        }
    }
}

// ---------------------------------------------------------------------------
// K3: per (b,h): scores via fp16 mma (64x64) + scalar borders,
// col softmax (poly exp, 2-way ILP), att0 -> ct_pre fp16
// ---------------------------------------------------------------------------
#define ASTR 72

__global__ __launch_bounds__(128) void attn_kernel(
    const __half* __restrict__ q16, __half* __restrict__ cp16o)
{
    __shared__ __align__(16) __half sQ[SEQL * ASTR];
    __shared__ float sc[SEQL][68];
    __shared__ float w0s[68];

    const int b = blockIdx.y, h = blockIdx.x;
    const int t = threadIdx.x, lane = t & 31, wid = t >> 5;
    const int gid = lane >> 2, tig = lane & 3;
    const __half* pq = q16 + (size_t)b * SEQL * EMBED + h * HDIM;

    for (int idx = t; idx < SEQL * 8; idx += 128) {
        int row = idx >> 3, c8 = (idx & 7) * 8;
        *(uint4*)(sQ + row * ASTR + c8) = *(const uint4*)(pq + (size_t)row * EMBED + c8);
    }
    __syncthreads();

    const uint32_t baseQ = (uint32_t)__cvta_generic_to_shared(&sQ[0]);
    const int m0 = wid * 16;
    const int aoff = (m0 + (lane & 15)) * ASTR + (lane >> 4) * 8;
    const int boffn = ((lane >> 4) << 3) + (lane & 7);
    const int boffk = ((lane >> 3) & 1) * 8;

    float acc[8][4];
    #pragma unroll
    for (int j = 0; j < 8; j++)
        #pragma unroll
        for (int k = 0; k < 4; k++) acc[j][k] = 0.f;

    #pragma unroll
    for (int kc = 0; kc < 4; kc++) {
        const int k0 = kc * 16;
        uint32_t ah[4];
        ldsm4(ah, baseQ + (uint32_t)((aoff + k0) * 2));
        #pragma unroll
        for (int p = 0; p < 4; p++) {
            uint32_t bb[4];
            ldsm4(bb, baseQ + (uint32_t)(((boffn + p * 16) * ASTR + k0 + boffk) * 2));
            mma16816h(acc[2 * p],     ah, bb);
            mma16816h(acc[2 * p + 1], ah, bb + 2);
        }
    }
    #pragma unroll
    for (int nt = 0; nt < 8; nt++) {
        int rr = m0 + gid, cc = nt * 8 + tig * 2;
        sc[rr][cc]         = acc[nt][0] * 0.125f;
        sc[rr][cc + 1]     = acc[nt][1] * 0.125f;
        sc[rr + 8][cc]     = acc[nt][2] * 0.125f;
        sc[rr + 8][cc + 1] = acc[nt][3] * 0.125f;
    }
    // row 64 (threads 63..127 -> cols 0..64)
    if (t >= 63) {
        int tt = t - 63;
        float a0 = 0.f, a1 = 0.f;
        #pragma unroll 4
        for (int k = 0; k < HDIM; k += 2) {
            a0 += __half2float(sQ[64 * ASTR + k]) * __half2float(sQ[tt * ASTR + k]);
            a1 += __half2float(sQ[64 * ASTR + k + 1]) * __half2float(sQ[tt * ASTR + k + 1]);
        }
        sc[64][tt] = (a0 + a1) * 0.125f;
    }
    __syncthreads();
    if (t < 64) sc[t][64] = sc[64][t];   // symmetry
    __syncthreads();

    if (t < SEQL) {
        float m0_ = -1e30f, m1_ = -1e30f;
        for (int s = 0; s < 64; s += 2) {
            m0_ = fmaxf(m0_, sc[s][t]);
            m1_ = fmaxf(m1_, sc[s + 1][t]);
        }
        float m = fmaxf(fmaxf(m0_, m1_), sc[64][t]);
        float Z0 = 0.f, Z1 = 0.f;
        for (int s = 0; s < 64; s += 2) {
            Z0 += fexp(sc[s][t] - m);
            Z1 += fexp(sc[s + 1][t] - m);
        }
        float Z = Z0 + Z1 + fexp(sc[64][t] - m);
        w0s[t] = fexp(sc[0][t] - m) / Z;
    }
    __syncthreads();

    if (t < HDIM) {
        float a0 = 0.f, a1 = 0.f;
        for (int s = 0; s < 64; s += 2) {
            a0 += w0s[s] * __half2float(sQ[s * ASTR + t]);
            a1 += w0s[s + 1] * __half2float(sQ[(s + 1) * ASTR + t]);
        }
        float a = a0 + a1 + w0s[64] * __half2float(sQ[64 * ASTR + t]);
        cp16o[(size_t)b * EMBED + h * HDIM + t] = __float2half(a);
    }
}

// logits: one CTA per batch row, one warp per class
__global__ __launch_bounds__(320) void logits_kernel(
    const float* __restrict__ h, const float* __restrict__ w2,
    const float* __restrict__ b2, float* __restrict__ out)
{
    int b = blockIdx.x;
    int lane = threadIdx.x & 31, w = threadIdx.x >> 5;
    const float* hb = h + (size_t)b * HID;
    float a = 0.f;
    for (int k = lane; k < HID; k += 32) a += hb[k] * w2[(size_t)w * HID + k];
    #pragma unroll
    for (int o = 16; o > 0; o >>= 1) a += __shfl_xor_sync(0xffffffffu, a, o);
    if (lane == 0) out[(size_t)b * NCLS + w] = a + b2[w];
}

extern "C" void kernel_launch(void* const* d_in, const int* in_sizes, int n_in,
                              void* d_out, int out_size)
{
    const float* x      = (const float*)d_in[0];
    const float* proj_w = (const float*)d_in[1];
    const float* proj_b = (const float*)d_in[2];
    const float* cls    = (const float*)d_in[3];
    const float* pos    = (const float*)d_in[4];
    const float* wq     = (const float*)d_in[5];
    const float* bq     = (const float*)d_in[6];
    const float* wo     = (const float*)d_in[7];
    const float* bo     = (const float*)d_in[8];
    const float* w1     = (const float*)d_in[9];
    const float* b1     = (const float*)d_in[10];
    const float* w2     = (const float*)d_in[11];
    const float* b2     = (const float*)d_in[12];
    float* out = (float*)d_out;

    __half *p_s, *p_wq, *p_wo, *p_w1, *p_q, *p_cp, *p_ct;
    float *p_h;
    cudaGetSymbolAddress((void**)&p_s, g_s16);
    cudaGetSymbolAddress((void**)&p_wq, g_wq16);
    cudaGetSymbolAddress((void**)&p_wo, g_wo16);
    cudaGetSymbolAddress((void**)&p_w1, g_w116);
    cudaGetSymbolAddress((void**)&p_q, g_q16);
    cudaGetSymbolAddress((void**)&p_cp, g_cp16);
    cudaGetSymbolAddress((void**)&p_ct, g_ct16);
    cudaGetSymbolAddress((void**)&p_h, g_h);

    // launch order keeps the q GEMM in ncu capture slot 4
    wprep_kernel<<<EMBED * EMBED / 256, 256>>>(wq, p_wq);                    // 1
    seq_kernel<<<BATCH, 256>>>(x, proj_w, proj_b, cls, pos, p_s);            // 2
    wprep_kernel<<<EMBED * EMBED / 256, 256>>>(wo, p_wo);                    // 3
    mma_gemm_kernel<<<dim3(EMBED / 128, MTOT / 128), 256>>>(                 // 4
        p_s, p_wq, bq, p_q, nullptr, EMBED, 0);
    attn_kernel<<<dim3(HEADS, BATCH), 128>>>(p_q, p_cp);                     // 5
    wprep_kernel<<<HID * EMBED / 256, 256>>>(w1, p_w1);                      // 6
    mma_gemm_kernel<<<dim3(EMBED / 128, BATCH / 128), 256>>>(                // 7
        p_cp, p_wo, bo, p_ct, nullptr, EMBED, 0);
    mma_gemm_kernel<<<dim3(HID / 128, BATCH / 128), 256>>>(                  // 8
        p_ct, p_w1, b1, nullptr, p_h, HID, 1);
    logits_kernel<<<BATCH, 320>>>(p_h, w2, b2, out);                         // 9
}

// round 11
// speedup vs baseline: 2.4880x; 1.2755x over previous
#include <cuda_runtime.h>
#include <cuda_fp16.h>
#include <math.h>
#include <stdint.h>

#define EMBED 512
#define HEADS 8
#define HDIM 64
#define SEQL 65
#define NPATCH 64
#define PFEAT 48
#define HID 1024
#define NCLS 10
#define BATCH 2048
#define MTOT (BATCH * SEQL)     // 133120
#define MP (BATCH * NPATCH)     // 131072 (patch GEMM rows)

// global scratch (no allocations allowed)
__device__ __align__(16) __half g_p16[(size_t)MP * 64];
__device__ __align__(16) __half g_pw16[EMBED * 64];
__device__ __align__(16) __half g_s16[(size_t)MTOT * EMBED];
__device__ __align__(16) __half g_wq16[EMBED * EMBED];
__device__ __align__(16) __half g_wo16[EMBED * EMBED];
__device__ __align__(16) __half g_w116[HID * EMBED];
__device__ __align__(16) __half g_q16[(size_t)MTOT * EMBED];
__device__ __align__(16) __half g_cp16[BATCH * EMBED];
__device__ __align__(16) __half g_ct16[BATCH * EMBED];
__device__ __align__(16) float g_h[BATCH * HID];

// ---------------- helpers ----------------
// fast exp: degree-5 Taylor of 2^f, rel err ~2.4e-6
__device__ __forceinline__ float fexp(float x) {
    x = fmaxf(x, -87.0f);
    float y = x * 1.4426950408889634f;
    int ir = __float2int_rn(y);
    float f = y - (float)ir;
    float p = 1.3333558146428443e-3f;
    p = fmaf(p, f, 9.618129107628477e-3f);
    p = fmaf(p, f, 5.55041086648216e-2f);
    p = fmaf(p, f, 2.402265069591007e-1f);
    p = fmaf(p, f, 6.931471805599453e-1f);
    p = fmaf(p, f, 1.0f);
    return p * __int_as_float((ir + 127) << 23);
}
// fp16 x fp16 -> fp32 accum MMA
__device__ __forceinline__ void mma16816h(float* c, const uint32_t* a,
                                          const uint32_t* b) {
    asm volatile(
        "mma.sync.aligned.m16n8k16.row.col.f32.f16.f16.f32 "
        "{%0,%1,%2,%3}, {%4,%5,%6,%7}, {%8,%9}, {%0,%1,%2,%3};"
        : "+f"(c[0]), "+f"(c[1]), "+f"(c[2]), "+f"(c[3])
        : "r"(a[0]), "r"(a[1]), "r"(a[2]), "r"(a[3]), "r"(b[0]), "r"(b[1]));
}
__device__ __forceinline__ void ldsm4(uint32_t* r, uint32_t addr) {
    asm volatile("ldmatrix.sync.aligned.m8n8.x4.shared.b16 {%0,%1,%2,%3}, [%4];"
                 : "=r"(r[0]), "=r"(r[1]), "=r"(r[2]), "=r"(r[3]) : "r"(addr));
}
__device__ __forceinline__ void cp16(uint32_t dst_smem, const void* src) {
    asm volatile("cp.async.ca.shared.global [%0], [%1], 16;"
                 :: "r"(dst_smem), "l"(src));
}
__device__ __forceinline__ void cpcommit() { asm volatile("cp.async.commit_group;"); }
__device__ __forceinline__ void cpwait0()  { asm volatile("cp.async.wait_group 0;"); }

// ---------------------------------------------------------------------------
// K1 "prep": fused patchify (p16, zero-padded K=64) + seq row0 + all weight
// conversions to fp16. Block ranges select the job.
// ---------------------------------------------------------------------------
#define PREP_PATCH 2048
#define PREP_PW    128     // 512*64/256
#define PREP_WQ    1024    // 512*512/256
#define PREP_WO    1024
#define PREP_W1    2048    // 1024*512/256
#define PREP_GRID (PREP_PATCH + PREP_PW + PREP_WQ + PREP_WO + PREP_W1)

__global__ __launch_bounds__(256) void prep_kernel(
    const float* __restrict__ x, const float* __restrict__ proj_w,
    const float* __restrict__ cls, const float* __restrict__ pos,
    const float* __restrict__ wq, const float* __restrict__ wo,
    const float* __restrict__ w1,
    __half* __restrict__ p16, __half* __restrict__ pw16,
    __half* __restrict__ s16, __half* __restrict__ wq16,
    __half* __restrict__ wo16, __half* __restrict__ w116)
{
    const int bid = blockIdx.x, t = threadIdx.x;
    if (bid < PREP_PATCH) {
        const int b = bid;
        const float* xb = x + (size_t)b * 3 * 32 * 32;
        __half* pb = p16 + (size_t)b * NPATCH * 64;
        // 64 patches x 48 feats
        for (int idx = t; idx < NPATCH * PFEAT; idx += 256) {
            int n = idx / PFEAT, f = idx % PFEAT;
            int c = f >> 4, r4 = (f >> 2) & 3, c4 = f & 3;
            int py = n >> 3, px = n & 7;
            pb[n * 64 + f] = __float2half(xb[c * 1024 + (py * 4 + r4) * 32 + (px * 4 + c4)]);
        }
        // zero pad cols 48..63
        for (int idx = t; idx < NPATCH * 16; idx += 256) {
            int n = idx >> 4, f = 48 + (idx & 15);
            pb[n * 64 + f] = __float2half(0.f);
        }
        // seq row 0 = cls + pos[0]
        for (int e = t; e < EMBED; e += 256)
            s16[(size_t)b * SEQL * EMBED + e] = __float2half(cls[e] + pos[e]);
        return;
    }
    int r = bid - PREP_PATCH;
    if (r < PREP_PW) {
        int idx = r * 256 + t;
        int row = idx >> 6, col = idx & 63;
        pw16[idx] = __float2half(col < PFEAT ? proj_w[row * PFEAT + col] : 0.f);
        return;
    }
    r -= PREP_PW;
    if (r < PREP_WQ) { int i = r * 256 + t; wq16[i] = __float2half(wq[i]); return; }
    r -= PREP_WQ;
    if (r < PREP_WO) { int i = r * 256 + t; wo16[i] = __float2half(wo[i]); return; }
    r -= PREP_WO;
    { int i = r * 256 + t; w116[i] = __float2half(w1[i]); }
}

// ---------------------------------------------------------------------------
// K2: fp16 MMA GEMM, K-chunk 64, double buffer, ONE barrier per chunk.
// CTA 128x128, 8 warps (4m x 2n), warp tile 32x64.
// mode 0: fp16 out; mode 1: fp32 + exact GELU; mode 2: fp16 out with
// row remap m -> (m/64)*65+1+(m%64) and += pos[(1+m%64)*EMBED + n].
// ---------------------------------------------------------------------------
#define QSTR 72
#define KC 64

__global__ __launch_bounds__(256, 2) void mma_gemm_kernel(
    const __half* __restrict__ A, int ldA,
    const __half* __restrict__ W, int ldW,
    const float* __restrict__ bias, const float* __restrict__ pos,
    __half* __restrict__ Ch, float* __restrict__ Cf,
    int ldC, int nchk, int mode)
{
    __shared__ __align__(16) __half sA[2][128 * QSTR];
    __shared__ __align__(16) __half sW[2][128 * QSTR];

    const int t = threadIdx.x;
    const int wid = t >> 5, lane = t & 31;
    const int gid = lane >> 2, tig = lane & 3;
    const int wm = wid & 3, wn = wid >> 2;
    const int m0 = blockIdx.y * 128, n0 = blockIdx.x * 128;

    float acc[2][8][4];
    #pragma unroll
    for (int i = 0; i < 2; i++)
        #pragma unroll
        for (int j = 0; j < 8; j++)
            #pragma unroll
            for (int k = 0; k < 4; k++) acc[i][j][k] = 0.f;

    const uint32_t stg = 128 * QSTR * 2;
    const uint32_t baseA = (uint32_t)__cvta_generic_to_shared(&sA[0][0]);
    const uint32_t baseW = (uint32_t)__cvta_generic_to_shared(&sW[0][0]);

    const int crow = t >> 3, ccol = (t & 7) * 8;
    auto issue = [&](int c, int s) {
        const uint32_t so = s * stg;
        const size_t ko = (size_t)c * KC + ccol;
        #pragma unroll
        for (int j = 0; j < 4; j++) {
            int row = crow + j * 32;
            uint32_t d = (uint32_t)((row * QSTR + ccol) * 2);
            cp16(baseA + so + d, A + (size_t)(m0 + row) * ldA + ko);
            cp16(baseW + so + d, W + (size_t)(n0 + row) * ldW + ko);
        }
        cpcommit();
    };

    const int aoff = (wm * 32 + (lane & 15)) * QSTR + (lane >> 4) * 8;
    const int boffn = wn * 64 + ((lane >> 4) << 3) + (lane & 7);
    const int boffk = ((lane >> 3) & 1) * 8;

    issue(0, 0);
    for (int c = 0; c < nchk; c++) {
        const int s = c & 1;
        cpwait0();
        __syncthreads();
        if (c + 1 < nchk) issue(c + 1, s ^ 1);
        const uint32_t so = s * stg;
        #pragma unroll
        for (int ks = 0; ks < 4; ks++) {
            const int k0 = ks * 16;
            uint32_t ah[2][4];
            #pragma unroll
            for (int mt = 0; mt < 2; mt++)
                ldsm4(ah[mt], baseA + so + (uint32_t)((aoff + mt * 16 * QSTR + k0) * 2));
            #pragma unroll
            for (int p = 0; p < 4; p++) {
                uint32_t bb[4];
                ldsm4(bb, baseW + so + (uint32_t)(((boffn + p * 16) * QSTR + k0 + boffk) * 2));
                #pragma unroll
                for (int mt = 0; mt < 2; mt++) {
                    mma16816h(acc[mt][2 * p],     ah[mt], bb);
                    mma16816h(acc[mt][2 * p + 1], ah[mt], bb + 2);
                }
            }
        }
    }

    __syncthreads();
    #pragma unroll
    for (int mt = 0; mt < 2; mt++) {
        int m1 = m0 + wm * 32 + mt * 16 + gid;   // rows m1, m1+8
        #pragma unroll
        for (int nt = 0; nt < 8; nt++) {
            int n = n0 + wn * 64 + nt * 8 + tig * 2;
            float b0 = bias[n], b1 = bias[n + 1];
            float v00 = acc[mt][nt][0] + b0, v01 = acc[mt][nt][1] + b1;
            float v10 = acc[mt][nt][2] + b0, v11 = acc[mt][nt][3] + b1;
            if (mode == 0) {
                __half2 H0; H0.x = __float2half(v00); H0.y = __float2half(v01);
                __half2 H1; H1.x = __float2half(v10); H1.y = __float2half(v11);
                *(__half2*)(Ch + (size_t)m1 * ldC + n)       = H0;
                *(__half2*)(Ch + (size_t)(m1 + 8) * ldC + n) = H1;
            } else if (mode == 1) {
                v00 = 0.5f * v00 * (1.f + erff(v00 * 0.70710678118654752f));
                v01 = 0.5f * v01 * (1.f + erff(v01 * 0.70710678118654752f));
                v10 = 0.5f * v10 * (1.f + erff(v10 * 0.70710678118654752f));
                v11 = 0.5f * v11 * (1.f + erff(v11 * 0.70710678118654752f));
                Cf[(size_t)m1 * ldC + n]           = v00;
                Cf[(size_t)m1 * ldC + n + 1]       = v01;
                Cf[(size_t)(m1 + 8) * ldC + n]     = v10;
                Cf[(size_t)(m1 + 8) * ldC + n + 1] = v11;
            } else {
                int pa = m1 & 63, pb = (m1 + 8) & 63;
                int ra = (m1 >> 6) * 65 + 1 + pa;
                int rb = ((m1 + 8) >> 6) * 65 + 1 + pb;
                v00 += pos[(1 + pa) * EMBED + n];
                v01 += pos[(1 + pa) * EMBED + n + 1];
                v10 += pos[(1 + pb) * EMBED + n];
                v11 += pos[(1 + pb) * EMBED + n + 1];
                __half2 H0; H0.x = __float2half(v00); H0.y = __float2half(v01);
                __half2 H1; H1.x = __float2half(v10); H1.y = __float2half(v11);
                *(__half2*)(Ch + (size_t)ra * ldC + n) = H0;
                *(__half2*)(Ch + (size_t)rb * ldC + n) = H1;
            }
        }
    }
}

// ---------------------------------------------------------------------------
// K3: per (b,h): scores via fp16 mma (64x64) + scalar borders,
// col softmax (poly exp, 2-way ILP), att0 -> ct_pre fp16
// ---------------------------------------------------------------------------
#define ASTR 72

__global__ __launch_bounds__(128) void attn_kernel(
    const __half* __restrict__ q16, __half* __restrict__ cp16o)
{
    __shared__ __align__(16) __half sQ[SEQL * ASTR];
    __shared__ float sc[SEQL][68];
    __shared__ float w0s[68];

    const int b = blockIdx.y, h = blockIdx.x;
    const int t = threadIdx.x, lane = t & 31, wid = t >> 5;
    const int gid = lane >> 2, tig = lane & 3;
    const __half* pq = q16 + (size_t)b * SEQL * EMBED + h * HDIM;

    for (int idx = t; idx < SEQL * 8; idx += 128) {
        int row = idx >> 3, c8 = (idx & 7) * 8;
        *(uint4*)(sQ + row * ASTR + c8) = *(const uint4*)(pq + (size_t)row * EMBED + c8);
    }
    __syncthreads();

    const uint32_t baseQ = (uint32_t)__cvta_generic_to_shared(&sQ[0]);
    const int m0 = wid * 16;
    const int aoff = (m0 + (lane & 15)) * ASTR + (lane >> 4) * 8;
    const int boffn = ((lane >> 4) << 3) + (lane & 7);
    const int boffk = ((lane >> 3) & 1) * 8;

    float acc[8][4];
    #pragma unroll
    for (int j = 0; j < 8; j++)
        #pragma unroll
        for (int k = 0; k < 4; k++) acc[j][k] = 0.f;

    #pragma unroll
    for (int kc = 0; kc < 4; kc++) {
        const int k0 = kc * 16;
        uint32_t ah[4];
        ldsm4(ah, baseQ + (uint32_t)((aoff + k0) * 2));
        #pragma unroll
        for (int p = 0; p < 4; p++) {
            uint32_t bb[4];
            ldsm4(bb, baseQ + (uint32_t)(((boffn + p * 16) * ASTR + k0 + boffk) * 2));
            mma16816h(acc[2 * p],     ah, bb);
            mma16816h(acc[2 * p + 1], ah, bb + 2);
        }
    }
    #pragma unroll
    for (int nt = 0; nt < 8; nt++) {
        int rr = m0 + gid, cc = nt * 8 + tig * 2;
        sc[rr][cc]         = acc[nt][0] * 0.125f;
        sc[rr][cc + 1]     = acc[nt][1] * 0.125f;
        sc[rr + 8][cc]     = acc[nt][2] * 0.125f;
        sc[rr + 8][cc + 1] = acc[nt][3] * 0.125f;
    }
    // row 64 (threads 63..127 -> cols 0..64)
    if (t >= 63) {
        int tt = t - 63;
        float a0 = 0.f, a1 = 0.f;
        #pragma unroll 4
        for (int k = 0; k < HDIM; k += 2) {
            a0 += __half2float(sQ[64 * ASTR + k]) * __half2float(sQ[tt * ASTR + k]);
            a1 += __half2float(sQ[64 * ASTR + k + 1]) * __half2float(sQ[tt * ASTR + k + 1]);
        }
        sc[64][tt] = (a0 + a1) * 0.125f;
    }
    __syncthreads();
    if (t < 64) sc[t][64] = sc[64][t];   // symmetry
    __syncthreads();

    if (t < SEQL) {
        float m0_ = -1e30f, m1_ = -1e30f;
        for (int s = 0; s < 64; s += 2) {
            m0_ = fmaxf(m0_, sc[s][t]);
            m1_ = fmaxf(m1_, sc[s + 1][t]);
        }
        float m = fmaxf(fmaxf(m0_, m1_), sc[64][t]);
        float Z0 = 0.f, Z1 = 0.f;
        for (int s = 0; s < 64; s += 2) {
            Z0 += fexp(sc[s][t] - m);
            Z1 += fexp(sc[s + 1][t] - m);
        }
        float Z = Z0 + Z1 + fexp(sc[64][t] - m);
        w0s[t] = fexp(sc[0][t] - m) / Z;
    }
    __syncthreads();

    if (t < HDIM) {
        float a0 = 0.f, a1 = 0.f;
        for (int s = 0; s < 64; s += 2) {
            a0 += w0s[s] * __half2float(sQ[s * ASTR + t]);
            a1 += w0s[s + 1] * __half2float(sQ[(s + 1) * ASTR + t]);
        }
        float a = a0 + a1 + w0s[64] * __half2float(sQ[64 * ASTR + t]);
        cp16o[(size_t)b * EMBED + h * HDIM + t] = __float2half(a);
    }
}

// logits: one CTA per batch row, one warp per class
__global__ __launch_bounds__(320) void logits_kernel(
    const float* __restrict__ h, const float* __restrict__ w2,
    const float* __restrict__ b2, float* __restrict__ out)
{
    int b = blockIdx.x;
    int lane = threadIdx.x & 31, w = threadIdx.x >> 5;
    const float* hb = h + (size_t)b * HID;
    float a = 0.f;
    for (int k = lane; k < HID; k += 32) a += hb[k] * w2[(size_t)w * HID + k];
    #pragma unroll
    for (int o = 16; o > 0; o >>= 1) a += __shfl_xor_sync(0xffffffffu, a, o);
    if (lane == 0) out[(size_t)b * NCLS + w] = a + b2[w];
}

extern "C" void kernel_launch(void* const* d_in, const int* in_sizes, int n_in,
                              void* d_out, int out_size)
{
    const float* x      = (const float*)d_in[0];
    const float* proj_w = (const float*)d_in[1];
    const float* proj_b = (const float*)d_in[2];
    const float* cls    = (const float*)d_in[3];
    const float* pos    = (const float*)d_in[4];
    const float* wq     = (const float*)d_in[5];
    const float* bq     = (const float*)d_in[6];
    const float* wo     = (const float*)d_in[7];
    const float* bo     = (const float*)d_in[8];
    const float* w1     = (const float*)d_in[9];
    const float* b1     = (const float*)d_in[10];
    const float* w2     = (const float*)d_in[11];
    const float* b2     = (const float*)d_in[12];
    float* out = (float*)d_out;

    __half *p_p, *p_pw, *p_s, *p_wq, *p_wo, *p_w1, *p_q, *p_cp, *p_ct;
    float *p_h;
    cudaGetSymbolAddress((void**)&p_p, g_p16);
    cudaGetSymbolAddress((void**)&p_pw, g_pw16);
    cudaGetSymbolAddress((void**)&p_s, g_s16);
    cudaGetSymbolAddress((void**)&p_wq, g_wq16);
    cudaGetSymbolAddress((void**)&p_wo, g_wo16);
    cudaGetSymbolAddress((void**)&p_w1, g_w116);
    cudaGetSymbolAddress((void**)&p_q, g_q16);
    cudaGetSymbolAddress((void**)&p_cp, g_cp16);
    cudaGetSymbolAddress((void**)&p_ct, g_ct16);
    cudaGetSymbolAddress((void**)&p_h, g_h);

    // 1: fused prep (patchify + row0 + all weight conversions)
    prep_kernel<<<PREP_GRID, 256>>>(x, proj_w, cls, pos, wq, wo, w1,
                                    p_p, p_pw, p_s, p_wq, p_wo, p_w1);
    // 2: emb GEMM -> s16 rows 1..64 per batch (mode 2: +pos, row remap)
    mma_gemm_kernel<<<dim3(EMBED / 128, MP / 128), 256>>>(
        p_p, 64, p_pw, 64, proj_b, pos, p_s, nullptr, EMBED, 1, 2);
    // 3: q GEMM
    mma_gemm_kernel<<<dim3(EMBED / 128, MTOT / 128), 256>>>(
        p_s, EMBED, p_wq, EMBED, bq, nullptr, p_q, nullptr, EMBED, 8, 0);
    // 4: attention (ncu capture slot)
    attn_kernel<<<dim3(HEADS, BATCH), 128>>>(p_q, p_cp);
    // 5: wo GEMM
    mma_gemm_kernel<<<dim3(EMBED / 128, BATCH / 128), 256>>>(
        p_cp, EMBED, p_wo, EMBED, bo, nullptr, p_ct, nullptr, EMBED, 8, 0);
    // 6: w1 GEMM + GELU
    mma_gemm_kernel<<<dim3(HID / 128, BATCH / 128), 256>>>(
        p_ct, EMBED, p_w1, EMBED, b1, nullptr, nullptr, p_h, HID, 8, 1);
    // 7: logits
    logits_kernel<<<BATCH, 320>>>(p_h, w2, b2, out);
}